// round 14
// baseline (speedup 1.0000x reference)
#include <cuda_runtime.h>
#include <cuda_bf16.h>
#include <cstdint>
#include <cstring>
#include <math.h>

// ---------------------------------------------------------------------------
// Problem constants
// ---------------------------------------------------------------------------
#define BGR   512
#define NPG   64
#define CNUM  8
#define MPG   128
#define CN    256
#define CE    64
#define EPG   200

#define NE_NODES (BGR*MPG)        // 65536
#define NE_EDGES (BGR*MPG*4)      // 262144
#define NN_NODES (BGR*NPG)        // 32768
#define NN_EDGES (BGR*EPG)        // 102400

#define OFF_OUT2 0
#define OFF_EI   ((size_t)NN_NODES*CN)
#define OFF_BR   (OFF_EI + (size_t)NN_EDGES*CE)
#define OFF_SN   (OFF_BR + (size_t)NE_NODES*CE)

// weight segment offsets (u32 pair units)
#define W_E1  0
#define W_E2  6144
#define W_WE1 12288
#define W_WE2 20480
#define W_N1  28672
#define W_N2  126976
#define W_TOT 225280

// ---------------------------------------------------------------------------
// Scratch (device globals)
// ---------------------------------------------------------------------------
__device__ float g_qE[(size_t)NE_NODES*CE];
__device__ float g_kE[(size_t)NE_NODES*CE];
__device__ float g_vE[(size_t)NE_NODES*CE];
__device__ float g_accE[(size_t)NE_NODES*CE];
__device__ float g_br1[(size_t)NE_NODES*CE];

__device__ float g_efbr[(size_t)NE_NODES*CN];
__device__ float g_efbr2[(size_t)NE_NODES*CN];
__device__ float g_qN[(size_t)NN_NODES*CN];
__device__ float g_kN[(size_t)NN_NODES*CN];
__device__ float g_vN[(size_t)NN_NODES*CN];
__device__ float g_accN[(size_t)NN_NODES*CN];
__device__ float g_out1[(size_t)NN_NODES*CN];

__device__ float g_bnpartE[(size_t)BGR * 2 * CE];
__device__ float g_bnpartN[(size_t)BGR * 2 * CN];
__device__ float g_muE[CE];
__device__ float g_rstdE[CE];
__device__ float g_muN[CN];
__device__ float g_rstdN[CN];

__device__ uint32_t g_ahiN[(size_t)NN_NODES*CN/2];
__device__ uint32_t g_aloN[(size_t)NN_NODES*CN/2];
__device__ uint32_t g_ahiE[(size_t)NE_NODES*CE/2];
__device__ uint32_t g_aloE[(size_t)NE_NODES*CE/2];
__device__ uint32_t g_ahiE2[(size_t)NE_NODES*CE/2];
__device__ uint32_t g_aloE2[(size_t)NE_NODES*CE/2];
__device__ uint32_t g_wthi[W_TOT];
__device__ uint32_t g_wtlo[W_TOT];

// precomputed CSR (packed adj: (src_local<<16)|edge_local)
__device__ int g_offE[(size_t)BGR * (MPG + 1)];
__device__ int g_adjE[(size_t)NE_EDGES];
__device__ int g_offN[(size_t)BGR * (NPG + 1)];
__device__ int g_adjN[(size_t)NN_EDGES];

// ---------------------------------------------------------------------------
// split helpers
// ---------------------------------------------------------------------------
__device__ __forceinline__ uint32_t pack_hi(float x, float y, float& rx, float& ry) {
    __nv_bfloat16 hx = __float2bfloat16(x), hy = __float2bfloat16(y);
    rx = x - __bfloat162float(hx);
    ry = y - __bfloat162float(hy);
    return (uint32_t)__bfloat16_as_ushort(hx) | ((uint32_t)__bfloat16_as_ushort(hy) << 16);
}
__device__ __forceinline__ uint32_t pack_lo(float rx, float ry) {
    __nv_bfloat16 lx = __float2bfloat16(rx), ly = __float2bfloat16(ry);
    return (uint32_t)__bfloat16_as_ushort(lx) | ((uint32_t)__bfloat16_as_ushort(ly) << 16);
}
__device__ __forceinline__ void split4(float4 v, uint2& hi, uint2& lo) {
    float r0, r1, r2, r3;
    hi.x = pack_hi(v.x, v.y, r0, r1);
    hi.y = pack_hi(v.z, v.w, r2, r3);
    lo.x = pack_lo(r0, r1);
    lo.y = pack_lo(r2, r3);
}

__global__ void split_bf16(const float2* __restrict__ a, uint32_t* __restrict__ hi,
                           uint32_t* __restrict__ lo, int n2) {
    int i = blockIdx.x * blockDim.x + threadIdx.x;
    if (i >= n2) return;
    float2 v = a[i];
    float rx, ry;
    hi[i] = pack_hi(v.x, v.y, rx, ry);
    lo[i] = pack_lo(rx, ry);
}

// All 8 weight matrices split in one launch, segmented layout.
__global__ void wsplit_all(
    const float* __restrict__ WqE1, const float* __restrict__ WkE1, const float* __restrict__ WvE1,
    const float* __restrict__ WqE2, const float* __restrict__ WkE2, const float* __restrict__ WvE2,
    const float* __restrict__ We1,  const float* __restrict__ We2,
    const float* __restrict__ Wq1,  const float* __restrict__ Wk1,  const float* __restrict__ Wv1,
    const float* __restrict__ Wq2,  const float* __restrict__ Wk2,  const float* __restrict__ Wv2,
    uint32_t* __restrict__ hi, uint32_t* __restrict__ lo)
{
    int i = blockIdx.x * blockDim.x + threadIdx.x;
    if (i >= W_TOT) return;
    const float* W; int Nper, n, kp;
    if (i < W_WE1) {
        int l = i / 6144, r = i % 6144;
        int mat = r / 2048, rr = r % 2048;
        n = rr / 32; kp = rr % 32; Nper = 64;
        const float* tab[6] = {WqE1, WkE1, WvE1, WqE2, WkE2, WvE2};
        W = tab[l * 3 + mat];
    } else if (i < W_N1) {
        int r = i - W_WE1;
        int l = r / 8192; r %= 8192;
        n = r / 32; kp = r % 32; Nper = 256;
        W = l ? We2 : We1;
    } else {
        int r = i - W_N1;
        int l = r / 98304; r %= 98304;
        int mat = r / 32768, rr = r % 32768;
        n = rr / 128; kp = rr % 128; Nper = 256;
        const float* tab[6] = {Wq1, Wk1, Wv1, Wq2, Wk2, Wv2};
        W = tab[l * 3 + mat];
    }
    float vx = W[(size_t)(2 * kp) * Nper + n];
    float vy = W[(size_t)(2 * kp + 1) * Nper + n];
    float rx, ry;
    hi[i] = pack_hi(vx, vy, rx, ry);
    lo[i] = pack_lo(rx, ry);
}

// ---------------------------------------------------------------------------
// CSR build (once per side): block per graph, packed adj
// ---------------------------------------------------------------------------
template <int NODES, int EDGES>
__global__ void csr_build(const int* __restrict__ src, const int* __restrict__ dst,
                          int* __restrict__ gOff, int* __restrict__ gAdj) {
    __shared__ int sOff[NODES + 1];
    __shared__ int sCur[NODES];
    const int g = blockIdx.x, t = threadIdx.x;
    const int nb = g * NODES, eb = g * EDGES;
    for (int i = t; i < NODES; i += 256) sCur[i] = 0;
    __syncthreads();
    for (int e = t; e < EDGES; e += 256) atomicAdd(&sCur[dst[eb + e] - nb], 1);
    __syncthreads();
    if (t == 0) {
        int run = 0;
        for (int i = 0; i < NODES; i++) { sOff[i] = run; run += sCur[i]; }
        sOff[NODES] = run;
    }
    __syncthreads();
    for (int i = t; i < NODES; i += 256) sCur[i] = sOff[i];
    __syncthreads();
    for (int e = t; e < EDGES; e += 256) {
        int d = dst[eb + e] - nb;
        int pos = atomicAdd(&sCur[d], 1);
        gAdj[eb + pos] = ((src[eb + e] - nb) << 16) | e;
    }
    for (int i = t; i < NODES + 1; i += 256) gOff[g * (NODES + 1) + i] = sOff[i];
}

// ---------------------------------------------------------------------------
// mma.sync + ldmatrix + cp.async
// ---------------------------------------------------------------------------
__device__ __forceinline__ void mma_bf16(float* c, const uint32_t* a,
                                         uint32_t b0, uint32_t b1) {
    asm volatile(
        "mma.sync.aligned.m16n8k16.row.col.f32.bf16.bf16.f32 "
        "{%0,%1,%2,%3}, {%4,%5,%6,%7}, {%8,%9}, {%0,%1,%2,%3};"
        : "+f"(c[0]), "+f"(c[1]), "+f"(c[2]), "+f"(c[3])
        : "r"(a[0]), "r"(a[1]), "r"(a[2]), "r"(a[3]), "r"(b0), "r"(b1));
}

__device__ __forceinline__ void ldsm_x4(uint32_t& r0, uint32_t& r1,
                                        uint32_t& r2, uint32_t& r3, uint32_t addr) {
    asm volatile("ldmatrix.sync.aligned.m8n8.x4.shared.b16 {%0,%1,%2,%3}, [%4];"
                 : "=r"(r0), "=r"(r1), "=r"(r2), "=r"(r3) : "r"(addr));
}

__device__ __forceinline__ uint32_t smem_u32(const void* p) {
    uint32_t a;
    asm("{ .reg .u64 t; cvta.to.shared.u64 t, %1; cvt.u32.u64 %0, t; }" : "=r"(a) : "l"(p));
    return a;
}

__device__ __forceinline__ void cp_async16(uint32_t saddr, const void* g) {
    asm volatile("cp.async.cg.shared.global [%0], [%1], 16;" :: "r"(saddr), "l"(g));
}
__device__ __forceinline__ void cp_commit() {
    asm volatile("cp.async.commit_group;" ::: "memory");
}
template<int N>
__device__ __forceinline__ void cp_wait() {
    asm volatile("cp.async.wait_group %0;" :: "n"(N) : "memory");
}

// ---------------------------------------------------------------------------
// HMMA split-bf16 GEMM: cp.async double-buffered pipeline (proven R11-R13).
// ---------------------------------------------------------------------------
template<int WM, int NWN>
__global__ void __launch_bounds__(256) hmma_gemm(
    const uint32_t* __restrict__ ahi, const uint32_t* __restrict__ alo,
    const uint32_t* __restrict__ bhi, const uint32_t* __restrict__ blo,
    float* __restrict__ C0, float* __restrict__ C1, float* __restrict__ C2,
    int M, int K, int Nper, int matdiv)
{
    constexpr int BN  = NWN * 64;
    constexpr int NWM = 8 / NWN;
    constexpr int BM  = NWM * WM * 16;
    constexpr int BUFSZ = (2 * BM + 2 * BN) * 20;
    const int K2 = K >> 1;

    extern __shared__ uint32_t sm[];
    const uint32_t smb = smem_u32(sm);

    const int t = threadIdx.x, warp = t >> 5, lane = t & 31;
    const int mat     = blockIdx.x / matdiv;
    const int colbase = (blockIdx.x % matdiv) * BN;
    const int bm = blockIdx.y * BM;
    const int wm = (warp % NWM) * WM * 16;
    const int wn = (warp / NWM) * 64;
    const int g4 = lane >> 2, t4 = lane & 3;

    const int aRow = (lane & 7) + ((lane >> 3) & 1) * 8;
    const int aKof = (lane >> 4) * 4;
    const int bRow = (lane & 7) + (lane >> 4) * 8;
    const int bKof = ((lane >> 3) & 1) * 4;

    const int brow_base = mat * Nper + colbase;

    auto stage = [&](int kc, int buf) {
        uint32_t base = smb + (uint32_t)buf * BUFSZ * 4;
        for (int idx = t; idx < BM * 4; idx += 256) {
            int r = idx >> 2, q = idx & 3;
            size_t gi = (size_t)(bm + r) * K2 + kc * 16 + q * 4;
            uint32_t so = (uint32_t)(r * 20 + q * 4) * 4;
            cp_async16(base + so, ahi + gi);
            cp_async16(base + (uint32_t)(BM * 20) * 4 + so, alo + gi);
        }
        for (int idx = t; idx < BN * 4; idx += 256) {
            int r = idx >> 2, q = idx & 3;
            size_t gi = (size_t)(brow_base + r) * K2 + kc * 16 + q * 4;
            uint32_t so = (uint32_t)(r * 20 + q * 4) * 4;
            cp_async16(base + (uint32_t)(2 * BM * 20) * 4 + so, bhi + gi);
            cp_async16(base + (uint32_t)((2 * BM + BN) * 20) * 4 + so, blo + gi);
        }
    };

    float acc[WM][8][4];
#pragma unroll
    for (int i = 0; i < WM; i++)
#pragma unroll
        for (int j = 0; j < 8; j++)
#pragma unroll
            for (int q = 0; q < 4; q++) acc[i][j][q] = 0.f;

    const int nch = K2 / 16;
    stage(0, 0);
    cp_commit();

    int buf = 0;
    for (int kc = 0; kc < nch; kc++) {
        if (kc + 1 < nch) {
            stage(kc + 1, buf ^ 1);
            cp_commit();
            cp_wait<1>();
        } else {
            cp_wait<0>();
        }
        __syncthreads();

        uint32_t base = smb + (uint32_t)buf * BUFSZ * 4;
        const uint32_t sAh = base;
        const uint32_t sAl = base + (uint32_t)(BM * 20) * 4;
        const uint32_t sBh = base + (uint32_t)(2 * BM * 20) * 4;
        const uint32_t sBl = base + (uint32_t)((2 * BM + BN) * 20) * 4;

#pragma unroll
        for (int ks = 0; ks < 2; ks++) {
            uint32_t afh[WM][4], afl[WM][4];
#pragma unroll
            for (int i = 0; i < WM; i++) {
                uint32_t off = ((uint32_t)((wm + i * 16 + aRow) * 20 + ks * 8 + aKof)) * 4;
                ldsm_x4(afh[i][0], afh[i][1], afh[i][2], afh[i][3], sAh + off);
                ldsm_x4(afl[i][0], afl[i][1], afl[i][2], afl[i][3], sAl + off);
            }
#pragma unroll
            for (int jp = 0; jp < 4; jp++) {
                uint32_t off = ((uint32_t)((wn + jp * 16 + bRow) * 20 + ks * 8 + bKof)) * 4;
                uint32_t bh0, bh1, bh2, bh3, bl0, bl1, bl2, bl3;
                ldsm_x4(bh0, bh1, bh2, bh3, sBh + off);
                ldsm_x4(bl0, bl1, bl2, bl3, sBl + off);
#pragma unroll
                for (int i = 0; i < WM; i++) {
                    mma_bf16(acc[i][2 * jp],     afh[i], bh0, bh1);
                    mma_bf16(acc[i][2 * jp],     afh[i], bl0, bl1);
                    mma_bf16(acc[i][2 * jp],     afl[i], bh0, bh1);
                    mma_bf16(acc[i][2 * jp + 1], afh[i], bh2, bh3);
                    mma_bf16(acc[i][2 * jp + 1], afh[i], bl2, bl3);
                    mma_bf16(acc[i][2 * jp + 1], afl[i], bh2, bh3);
                }
            }
        }
        __syncthreads();
        buf ^= 1;
    }

    float* __restrict__ Cout = (mat == 0) ? C0 : (mat == 1) ? C1 : C2;
#pragma unroll
    for (int i = 0; i < WM; i++) {
        int r0 = bm + wm + i * 16 + g4;
#pragma unroll
        for (int j = 0; j < 8; j++) {
            int c = colbase + wn + j * 8 + 2 * t4;
            float2 v0 = {acc[i][j][0], acc[i][j][1]};
            float2 v1 = {acc[i][j][2], acc[i][j][3]};
            *(float2*)&Cout[(size_t)r0 * Nper + c]       = v0;
            *(float2*)&Cout[(size_t)(r0 + 8) * Nper + c] = v1;
        }
    }
}

// ---------------------------------------------------------------------------
// ef row mapping (N-side)
// ---------------------------------------------------------------------------
__device__ __forceinline__ const float* ef_row(const float* __restrict__ efbr,
                                               const float* __restrict__ we0,
                                               int g, int e) {
    if (e < 2 * CNUM)       return efbr + ((size_t)g * MPG + (e >> 1)) * CN;
    if (e < 2 * CNUM + NPG) return we0;
    return efbr + ((size_t)g * MPG + e - (CNUM + NPG)) * CN;
}

// ---------------------------------------------------------------------------
// Fused attention conv: precomputed CSR, v staged in smem, vectorized loads.
// Dynamic smem layout: sOff | sAdj | sW | sSumW | sBN | (pad) | sV
// ---------------------------------------------------------------------------
template <int C, int H, int NODES, int EDGES, bool HAS_EF>
__global__ void __launch_bounds__(256) attn_conv(
    const float* __restrict__ q, const float* __restrict__ k,
    const float* __restrict__ v,
    const float* __restrict__ efbr, const float* __restrict__ we0,
    const int* __restrict__ gOff, const int* __restrict__ gAdj,
    float* __restrict__ outbuf, float* __restrict__ bnpart, float scale)
{
    constexpr int Oh = C / H;
    constexpr int WA = Oh / 8;
    constexpr int WB = C / 32;
    constexpr int HDR  = (NODES + 1) + EDGES + EDGES * H + 32 + 2 * C;
    constexpr int HDRA = (HDR + 3) & ~3;

    extern __shared__ char smraw[];
    int*   sOff  = (int*)smraw;                      // NODES+1
    int*   sAdj  = sOff + NODES + 1;                 // EDGES (packed)
    float* sW    = (float*)(sAdj + EDGES);           // EDGES*H
    float* sSumW = sW + EDGES * H;                   // 32
    float* sBN   = sSumW + 32;                       // 2*C
    float* sV    = (float*)smraw + HDRA;             // NODES*C

    const int g = blockIdx.x, t = threadIdx.x;
    const int nb = g * NODES, eb = g * EDGES;
    const int warp = t >> 5, lane = t & 31;

    for (int i = t; i < NODES + 1; i += 256) sOff[i] = gOff[g * (NODES + 1) + i];
    for (int i = t; i < EDGES; i += 256) sAdj[i] = gAdj[eb + i];
    for (int i = t; i < 2 * C; i += 256) sBN[i] = 0.f;
    {
        const float4* vg = (const float4*)(v + (size_t)nb * C);
        float4* vs = (float4*)sV;
        for (int i = t; i < NODES * C / 4; i += 256) vs[i] = vg[i];
    }
    __syncthreads();

    const int h = lane >> 3, u = lane & 7;
    const int cA = h * Oh + u * WA;
    const int cB = lane * WB;
    const int headB = cB / Oh;

    float s1[WB], s2[WB];
#pragma unroll
    for (int j = 0; j < WB; j++) { s1[j] = 0.f; s2[j] = 0.f; }

    for (int d = warp; d < NODES; d += 8) {
        const int e0 = sOff[d], e1 = sOff[d + 1];

        float qv[WA];
        {
            const float* qr = q + (size_t)(nb + d) * C + cA;
            if constexpr (WA == 8) {
                float4 a = *(const float4*)qr, b = *(const float4*)(qr + 4);
                qv[0] = a.x; qv[1] = a.y; qv[2] = a.z; qv[3] = a.w;
                qv[4] = b.x; qv[5] = b.y; qv[6] = b.z; qv[7] = b.w;
            } else {
                float2 a = *(const float2*)qr;
                qv[0] = a.x; qv[1] = a.y;
            }
        }

        // ---- phase 1: logits + max ----
        float mx = -INFINITY;
        for (int ii = e0; ii < e1; ii++) {
            int pk = sAdj[ii];
            int e = pk & 0xffff, s = pk >> 16;
            const float* kr = k + (size_t)(nb + s) * C + cA;
            float kk[WA];
            if constexpr (WA == 8) {
                float4 a = *(const float4*)kr, b = *(const float4*)(kr + 4);
                kk[0] = a.x; kk[1] = a.y; kk[2] = a.z; kk[3] = a.w;
                kk[4] = b.x; kk[5] = b.y; kk[6] = b.z; kk[7] = b.w;
            } else {
                float2 a = *(const float2*)kr;
                kk[0] = a.x; kk[1] = a.y;
            }
            if (HAS_EF) {
                const float* er = ef_row(efbr, we0, g, e) + cA;
                if constexpr (WA == 8) {
                    float4 a = *(const float4*)er, b = *(const float4*)(er + 4);
                    kk[0] += a.x; kk[1] += a.y; kk[2] += a.z; kk[3] += a.w;
                    kk[4] += b.x; kk[5] += b.y; kk[6] += b.z; kk[7] += b.w;
                } else {
                    float2 a = *(const float2*)er;
                    kk[0] += a.x; kk[1] += a.y;
                }
            }
            float p = 0.f;
#pragma unroll
            for (int j = 0; j < WA; j++) p += qv[j] * kk[j];
            p += __shfl_xor_sync(0xffffffffu, p, 1);
            p += __shfl_xor_sync(0xffffffffu, p, 2);
            p += __shfl_xor_sync(0xffffffffu, p, 4);
            float l = p * scale;
            l = (l > 0.f) ? l : 0.2f * l;
            if (u == 0) sW[e * H + h] = l;
            mx = fmaxf(mx, l);
        }
        __syncwarp();

        // ---- phase 2: weights + per-head sum ----
        float sumh = 0.f;
        for (int ii = e0; ii < e1; ii++) {
            int e = sAdj[ii] & 0xffff;
            float w = expf(sW[e * H + h] - mx);
            if (u == 0) sW[e * H + h] = w;
            sumh += w;
        }
        if (u == 0) sSumW[warp * H + h] = sumh;
        __syncwarp();

        // ---- phase 3: accumulate w * (v + ef) ----
        float acc[WB];
#pragma unroll
        for (int j = 0; j < WB; j++) acc[j] = 0.f;
        for (int ii = e0; ii < e1; ii++) {
            int pk = sAdj[ii];
            int e = pk & 0xffff, s = pk >> 16;
            const float w = sW[e * H + headB];
            const float* vr = sV + s * C + cB;
            float vv[WB];
            if constexpr (WB == 8) {
                float4 a = *(const float4*)vr, b = *(const float4*)(vr + 4);
                vv[0] = a.x; vv[1] = a.y; vv[2] = a.z; vv[3] = a.w;
                vv[4] = b.x; vv[5] = b.y; vv[6] = b.z; vv[7] = b.w;
            } else {
                float2 a = *(const float2*)vr;
                vv[0] = a.x; vv[1] = a.y;
            }
            if (HAS_EF) {
                const float* er = ef_row(efbr, we0, g, e) + cB;
                if constexpr (WB == 8) {
                    float4 a = *(const float4*)er, b = *(const float4*)(er + 4);
                    vv[0] += a.x; vv[1] += a.y; vv[2] += a.z; vv[3] += a.w;
                    vv[4] += b.x; vv[5] += b.y; vv[6] += b.z; vv[7] += b.w;
                } else {
                    float2 a = *(const float2*)er;
                    vv[0] += a.x; vv[1] += a.y;
                }
            }
#pragma unroll
            for (int j = 0; j < WB; j++) acc[j] += w * vv[j];
        }

        // ---- phase 4: normalize + write + BN partials ----
        const float denom = sSumW[warp * H + headB] + 1e-16f;
        float* orow = outbuf + (size_t)(nb + d) * C + cB;
        float o[WB];
#pragma unroll
        for (int j = 0; j < WB; j++) {
            o[j] = acc[j] / denom;
            s1[j] += o[j]; s2[j] += o[j] * o[j];
        }
        if constexpr (WB == 8) {
            *(float4*)orow       = make_float4(o[0], o[1], o[2], o[3]);
            *(float4*)(orow + 4) = make_float4(o[4], o[5], o[6], o[7]);
        } else {
            *(float2*)orow = make_float2(o[0], o[1]);
        }
    }

#pragma unroll
    for (int j = 0; j < WB; j++) {
        atomicAdd(&sBN[cB + j], s1[j]);
        atomicAdd(&sBN[C + cB + j], s2[j]);
    }
    __syncthreads();
    for (int i = t; i < 2 * C; i += 256)
        bnpart[(size_t)g * 2 * C + i] = sBN[i];
}

// smem sizes for attn_conv
#define ATTN_SMEM_N ((((NPG + 1) + EPG + EPG * 4 + 32 + 2 * CN + 3) & ~3) * 4 + NPG * CN * 4)
#define ATTN_SMEM_E ((((MPG + 1) + MPG * 4 + MPG * 4 * 4 + 32 + 2 * CE + 3) & ~3) * 4 + MPG * CE * 4)

// ---------------------------------------------------------------------------
// BN stats reduce, parallel over channels (grid = C)
// ---------------------------------------------------------------------------
template <int C>
__global__ void bn_final3(const float* __restrict__ part,
                          float* __restrict__ mu, float* __restrict__ rstd,
                          int nblocks, int Nrows) {
    __shared__ float rs[256], rss[256];
    int c = blockIdx.x, t = threadIdx.x;
    float s = 0.f, ss = 0.f;
    for (int b = t; b < nblocks; b += 256) {
        s  += part[(size_t)b * 2 * C + c];
        ss += part[(size_t)b * 2 * C + C + c];
    }
    rs[t] = s; rss[t] = ss;
    __syncthreads();
    for (int o = 128; o > 0; o >>= 1) {
        if (t < o) { rs[t] += rs[t + o]; rss[t] += rss[t + o]; }
        __syncthreads();
    }
    if (t == 0) {
        float m = rs[0] / (float)Nrows;
        float v = rss[0] / (float)Nrows - m * m;
        mu[c] = m;
        rstd[c] = rsqrtf(v + 1e-5f);
    }
}

// ---------------------------------------------------------------------------
// BN apply variants (float4), with fused bf16 split outputs
// ---------------------------------------------------------------------------
template <int C, bool SUB>
__global__ void bn_apply4s(const float4* __restrict__ o, const float4* __restrict__ res,
                           const float* __restrict__ mu, const float* __restrict__ rstd,
                           const float* __restrict__ g, const float* __restrict__ b,
                           float4* __restrict__ out,
                           uint2* __restrict__ shi, uint2* __restrict__ slo, int n4) {
    int i = blockIdx.x * blockDim.x + threadIdx.x;
    if (i >= n4) return;
    int c = (i % (C / 4)) * 4;
    float4 ov = o[i], rv = res[i], y;
    y.x = fmaxf((ov.x - mu[c+0]) * rstd[c+0] * g[c+0] + b[c+0], 0.f);
    y.y = fmaxf((ov.y - mu[c+1]) * rstd[c+1] * g[c+1] + b[c+1], 0.f);
    y.z = fmaxf((ov.z - mu[c+2]) * rstd[c+2] * g[c+2] + b[c+2], 0.f);
    y.w = fmaxf((ov.w - mu[c+3]) * rstd[c+3] * g[c+3] + b[c+3], 0.f);
    float4 r;
    if (SUB) { r.x = rv.x - y.x; r.y = rv.y - y.y; r.z = rv.z - y.z; r.w = rv.w - y.w; }
    else     { r.x = rv.x + y.x; r.y = rv.y + y.y; r.z = rv.z + y.z; r.w = rv.w + y.w; }
    out[i] = r;
    uint2 hi, lo;
    split4(r, hi, lo);
    shi[i] = hi; slo[i] = lo;
}

__global__ void bn_apply_toedge4(const float4* __restrict__ o, const float4* __restrict__ res,
                                 const float* __restrict__ mu, const float* __restrict__ rstd,
                                 const float* __restrict__ gg, const float* __restrict__ bb,
                                 float4* __restrict__ brout, float4* __restrict__ ei,
                                 uint2* __restrict__ shi, uint2* __restrict__ slo) {
    int i = blockIdx.x * blockDim.x + threadIdx.x;
    if (i >= NE_NODES * (CE / 4)) return;
    int c4 = i & 15, c = c4 * 4;
    int row = i >> 4;
    int g = row >> 7, r = row & 127;
    float4 ov = o[i], rv = res[i], val;
    val.x = rv.x - fmaxf((ov.x - mu[c+0]) * rstd[c+0] * gg[c+0] + bb[c+0], 0.f);
    val.y = rv.y - fmaxf((ov.y - mu[c+1]) * rstd[c+1] * gg[c+1] + bb[c+1], 0.f);
    val.z = rv.z - fmaxf((ov.z - mu[c+2]) * rstd[c+2] * gg[c+2] + bb[c+2], 0.f);
    val.w = rv.w - fmaxf((ov.w - mu[c+3]) * rstd[c+3] * gg[c+3] + bb[c+3], 0.f);
    brout[i] = val;
    uint2 hi, lo;
    split4(val, hi, lo);
    shi[i] = hi; slo[i] = lo;
    size_t eib = (size_t)g * EPG;
    if (r < CNUM) {
        ei[(eib + 2 * r) * 16 + c4]     = val;
        ei[(eib + 2 * r + 1) * 16 + c4] = val;
    } else {
        ei[(eib + r + (CNUM + NPG)) * 16 + c4] = val;
    }
}

__global__ void bn_apply_sn4(const float4* __restrict__ o, const float4* __restrict__ res,
                             const float* __restrict__ mu, const float* __restrict__ rstd,
                             const float* __restrict__ gg, const float* __restrict__ bb,
                             float4* __restrict__ out, float4* __restrict__ sn) {
    int i = blockIdx.x * blockDim.x + threadIdx.x;
    if (i >= NN_NODES * (CN / 4)) return;
    int c4 = i & 63, c = c4 * 4;
    int row = i >> 6;
    float4 ov = o[i], rv = res[i], val;
    val.x = rv.x - fmaxf((ov.x - mu[c+0]) * rstd[c+0] * gg[c+0] + bb[c+0], 0.f);
    val.y = rv.y - fmaxf((ov.y - mu[c+1]) * rstd[c+1] * gg[c+1] + bb[c+1], 0.f);
    val.z = rv.z - fmaxf((ov.z - mu[c+2]) * rstd[c+2] * gg[c+2] + bb[c+2], 0.f);
    val.w = rv.w - fmaxf((ov.w - mu[c+3]) * rstd[c+3] * gg[c+3] + bb[c+3], 0.f);
    out[i] = val;
    if ((row & 63) == 63) sn[(size_t)(row >> 6) * 64 + c4] = val;
}

__global__ void onehot_fill(float* __restrict__ ei) {
    int i = blockIdx.x * blockDim.x + threadIdx.x;
    if (i >= BGR * NPG * CE) return;
    int c = i % CE;
    int row = i / CE;
    int g = row / NPG, rr = row % NPG;
    ei[((size_t)g * EPG + 2 * CNUM + rr) * CE + c] = (c == 0) ? 1.f : 0.f;
}

// ---------------------------------------------------------------------------
// Host orchestration (two streams, event fork/join)
// ---------------------------------------------------------------------------
static inline float* sym(const void* s) {
    void* p = nullptr;
    cudaGetSymbolAddress(&p, (const void*)s);
    return (float*)p;
}

static cudaStream_t make_stream() {
    cudaStream_t s;
    cudaStreamCreateWithFlags(&s, cudaStreamNonBlocking);
    return s;
}
static cudaEvent_t make_event() {
    cudaEvent_t e;
    cudaEventCreateWithFlags(&e, cudaEventDisableTiming);
    return e;
}

extern "C" void kernel_launch(void* const* d_in, const int* in_sizes, int n_in,
                              void* d_out, int out_size) {
    (void)in_sizes; (void)n_in; (void)out_size;
    const float* x    = (const float*)d_in[0];
    const int*   eiN  = (const int*)d_in[1];
    const float* brf  = (const float*)d_in[2];
    const int*   eiE  = (const int*)d_in[3];
    const float* WqE1 = (const float*)d_in[4];
    const float* WkE1 = (const float*)d_in[5];
    const float* WvE1 = (const float*)d_in[6];
    const float* gE1  = (const float*)d_in[7];
    const float* bE1  = (const float*)d_in[8];
    const float* Wq1  = (const float*)d_in[9];
    const float* Wk1  = (const float*)d_in[10];
    const float* Wv1  = (const float*)d_in[11];
    const float* We1  = (const float*)d_in[12];
    const float* gN1  = (const float*)d_in[13];
    const float* bN1  = (const float*)d_in[14];
    const float* WqE2 = (const float*)d_in[15];
    const float* WkE2 = (const float*)d_in[16];
    const float* WvE2 = (const float*)d_in[17];
    const float* gE2  = (const float*)d_in[18];
    const float* bE2  = (const float*)d_in[19];
    const float* Wq2  = (const float*)d_in[20];
    const float* Wk2  = (const float*)d_in[21];
    const float* Wv2  = (const float*)d_in[22];
    const float* We2  = (const float*)d_in[23];
    const float* gN2  = (const float*)d_in[24];
    const float* bN2  = (const float*)d_in[25];

    float* out = (float*)d_out;
    float* out2_buf = out + OFF_OUT2;
    float* ei2_buf  = out + OFF_EI;
    float* br2_buf  = out + OFF_BR;
    float* sn_buf   = out + OFF_SN;

    float* qE   = sym(g_qE);   float* kE   = sym(g_kE);   float* vE  = sym(g_vE);
    float* accE = sym(g_accE); float* br1  = sym(g_br1);
    float* efbr = sym(g_efbr); float* efbr2 = sym(g_efbr2);
    float* qN   = sym(g_qN);   float* kN   = sym(g_kN);   float* vN  = sym(g_vN);
    float* accN = sym(g_accN); float* out1 = sym(g_out1);
    float* bnpartE = sym(g_bnpartE); float* bnpartN = sym(g_bnpartN);
    float* muE = sym(g_muE); float* rstdE = sym(g_rstdE);
    float* muN = sym(g_muN); float* rstdN = sym(g_rstdN);
    uint32_t* ahiN = (uint32_t*)sym(g_ahiN); uint32_t* aloN = (uint32_t*)sym(g_aloN);
    uint32_t* ahiE = (uint32_t*)sym(g_ahiE); uint32_t* aloE = (uint32_t*)sym(g_aloE);
    uint32_t* ahiE2 = (uint32_t*)sym(g_ahiE2); uint32_t* aloE2 = (uint32_t*)sym(g_aloE2);
    uint32_t* whi = (uint32_t*)sym(g_wthi); uint32_t* wlo = (uint32_t*)sym(g_wtlo);
    int* offE = (int*)sym(g_offE); int* adjE = (int*)sym(g_adjE);
    int* offN = (int*)sym(g_offN); int* adjN = (int*)sym(g_adjN);

    const int* srcE = eiE;              const int* dstE = eiE + NE_EDGES;
    const int* srcN = eiN;              const int* dstN = eiN + NN_EDGES;

    const float scaleE = 0.25f;
    const float scaleN = 0.125f;

    const int nE2 = NE_NODES * CE / 2;
    const int nN2 = NN_NODES * CN / 2;
    const int nE4 = NE_NODES * CE / 4;
    const int nN4 = NN_NODES * CN / 4;

    const int SME = 2 * (2 * 256 + 2 * 64) * 20 * 4;    // 102400
    const int SMN = 2 * (2 * 128 + 2 * 128) * 20 * 4;   // 81920
    cudaFuncSetAttribute(hmma_gemm<2, 1>, cudaFuncAttributeMaxDynamicSharedMemorySize, SME);
    cudaFuncSetAttribute(hmma_gemm<2, 2>, cudaFuncAttributeMaxDynamicSharedMemorySize, SMN);
    cudaFuncSetAttribute(attn_conv<CN, 4, NPG, EPG, true>,
                         cudaFuncAttributeMaxDynamicSharedMemorySize, ATTN_SMEM_N);
    cudaFuncSetAttribute(attn_conv<CE, 4, MPG, MPG * 4, false>,
                         cudaFuncAttributeMaxDynamicSharedMemorySize, ATTN_SMEM_E);

    static cudaStream_t s2 = make_stream();
    static cudaEvent_t evW   = make_event();
    static cudaEvent_t evQN1 = make_event();
    static cudaEvent_t evBr1 = make_event();
    static cudaEvent_t evEf2 = make_event();

    // ===== main: CSR + weights + constants + brf split =====
    csr_build<MPG, MPG * 4><<<BGR, 256>>>(srcE, dstE, offE, adjE);
    csr_build<NPG, EPG><<<BGR, 256>>>(srcN, dstN, offN, adjN);
    wsplit_all<<<(W_TOT + 255) / 256, 256>>>(WqE1, WkE1, WvE1, WqE2, WkE2, WvE2,
                                             We1, We2, Wq1, Wk1, Wv1, Wq2, Wk2, Wv2,
                                             whi, wlo);
    onehot_fill<<<(BGR * NPG * CE) / 256, 256>>>(ei2_buf);
    split_bf16<<<(nE2 + 255) / 256, 256>>>((const float2*)brf, ahiE, aloE, nE2);
    cudaEventRecord(evW, 0);
    cudaStreamWaitEvent(s2, evW, 0);

    // ===== stream2: N1 prep =====
    split_bf16<<<(nN2 + 255) / 256, 256, 0, s2>>>((const float2*)x, ahiN, aloN, nN2);
    hmma_gemm<2, 2><<<dim3(6, NN_NODES / 128), 256, SMN, s2>>>(
        ahiN, aloN, whi + W_N1, wlo + W_N1, qN, kN, vN, NN_NODES, CN, 256, 2);
    cudaEventRecord(evQN1, s2);

    // ===== main: E1 chain =====
    hmma_gemm<2, 1><<<dim3(3, NE_NODES / 256), 256, SME>>>(
        ahiE, aloE, whi + W_E1, wlo + W_E1, qE, kE, vE, NE_NODES, CE, 64, 1);
    attn_conv<CE, 4, MPG, MPG * 4, false><<<BGR, 256, ATTN_SMEM_E>>>(
        qE, kE, vE, nullptr, nullptr, offE, adjE, accE, bnpartE, scaleE);
    bn_final3<CE><<<CE, 256>>>(bnpartE, muE, rstdE, BGR, NE_NODES);
    bn_apply4s<CE, false><<<nE4 / 256, 256>>>(
        (const float4*)accE, (const float4*)brf, muE, rstdE, gE1, bE1,
        (float4*)br1, (uint2*)ahiE, (uint2*)aloE, nE4);
    cudaEventRecord(evBr1, 0);
    cudaStreamWaitEvent(s2, evBr1, 0);

    // ===== main: ef1 + N1 attn chain =====
    hmma_gemm<2, 2><<<dim3(2, NE_NODES / 128), 256, SMN>>>(
        ahiE, aloE, whi + W_WE1, wlo + W_WE1, efbr, efbr, efbr, NE_NODES, CE, 256, 2);
    cudaStreamWaitEvent(0, evQN1, 0);
    attn_conv<CN, 4, NPG, EPG, true><<<BGR, 256, ATTN_SMEM_N>>>(
        qN, kN, vN, efbr, We1, offN, adjN, accN, bnpartN, scaleN);
    bn_final3<CN><<<CN, 256>>>(bnpartN, muN, rstdN, BGR, NN_NODES);
    bn_apply4s<CN, false><<<nN4 / 256, 256>>>(
        (const float4*)accN, (const float4*)x, muN, rstdN, gN1, bN1,
        (float4*)out1, (uint2*)ahiN, (uint2*)aloN, nN4);

    // ===== stream2: E2 chain =====
    hmma_gemm<2, 1><<<dim3(3, NE_NODES / 256), 256, SME, s2>>>(
        ahiE, aloE, whi + W_E2, wlo + W_E2, qE, kE, vE, NE_NODES, CE, 64, 1);
    attn_conv<CE, 4, MPG, MPG * 4, false><<<BGR, 256, ATTN_SMEM_E, s2>>>(
        qE, kE, vE, nullptr, nullptr, offE, adjE, accE, bnpartE, scaleE);
    bn_final3<CE><<<CE, 256, 0, s2>>>(bnpartE, muE, rstdE, BGR, NE_NODES);
    bn_apply_toedge4<<<nE4 / 256, 256, 0, s2>>>(
        (const float4*)accE, (const float4*)br1, muE, rstdE, gE2, bE2,
        (float4*)br2_buf, (float4*)ei2_buf, (uint2*)ahiE2, (uint2*)aloE2);
    hmma_gemm<2, 2><<<dim3(2, NE_NODES / 128), 256, SMN, s2>>>(
        ahiE2, aloE2, whi + W_WE2, wlo + W_WE2, efbr2, efbr2, efbr2, NE_NODES, CE, 256, 2);
    cudaEventRecord(evEf2, s2);

    // ===== main: N2 chain =====
    hmma_gemm<2, 2><<<dim3(6, NN_NODES / 128), 256, SMN>>>(
        ahiN, aloN, whi + W_N2, wlo + W_N2, qN, kN, vN, NN_NODES, CN, 256, 2);
    cudaStreamWaitEvent(0, evEf2, 0);
    attn_conv<CN, 4, NPG, EPG, true><<<BGR, 256, ATTN_SMEM_N>>>(
        qN, kN, vN, efbr2, We2, offN, adjN, accN, bnpartN, scaleN);
    bn_final3<CN><<<CN, 256>>>(bnpartN, muN, rstdN, BGR, NN_NODES);
    bn_apply_sn4<<<nN4 / 256, 256>>>(
        (const float4*)accN, (const float4*)out1, muN, rstdN, gN2, bN2,
        (float4*)out2_buf, (float4*)sn_buf);
}

// round 15
// speedup vs baseline: 1.0459x; 1.0459x over previous
#include <cuda_runtime.h>
#include <cuda_bf16.h>
#include <cstdint>
#include <cstring>
#include <math.h>

// ---------------------------------------------------------------------------
// Problem constants
// ---------------------------------------------------------------------------
#define BGR   512
#define NPG   64
#define CNUM  8
#define MPG   128
#define CN    256
#define CE    64
#define EPG   200

#define NE_NODES (BGR*MPG)        // 65536
#define NE_EDGES (BGR*MPG*4)      // 262144
#define NN_NODES (BGR*NPG)        // 32768
#define NN_EDGES (BGR*EPG)        // 102400

#define OFF_OUT2 0
#define OFF_EI   ((size_t)NN_NODES*CN)
#define OFF_BR   (OFF_EI + (size_t)NN_EDGES*CE)
#define OFF_SN   (OFF_BR + (size_t)NE_NODES*CE)

// weight segment offsets (u32 pair units)
#define W_E1  0
#define W_E2  6144
#define W_WE1 12288
#define W_WE2 20480
#define W_N1  28672
#define W_N2  126976
#define W_TOT 225280

// ---------------------------------------------------------------------------
// Scratch (device globals)
// ---------------------------------------------------------------------------
__device__ float g_qE[(size_t)NE_NODES*CE];
__device__ float g_kE[(size_t)NE_NODES*CE];
__device__ float g_vE[(size_t)NE_NODES*CE];
__device__ float g_accE[(size_t)NE_NODES*CE];
__device__ float g_br1[(size_t)NE_NODES*CE];

__device__ float g_efbr[(size_t)NE_NODES*CN];
__device__ float g_efbr2[(size_t)NE_NODES*CN];
__device__ float g_qN[(size_t)NN_NODES*CN];
__device__ float g_kN[(size_t)NN_NODES*CN];
__device__ float g_vN[(size_t)NN_NODES*CN];
__device__ float g_accN[(size_t)NN_NODES*CN];
__device__ float g_out1[(size_t)NN_NODES*CN];

__device__ float g_bnpartE[(size_t)BGR * 2 * CE];
__device__ float g_bnpartN[(size_t)BGR * 2 * CN];
__device__ float g_muE[CE];
__device__ float g_rstdE[CE];
__device__ float g_muN[CN];
__device__ float g_rstdN[CN];

__device__ uint32_t g_ahiN[(size_t)NN_NODES*CN/2];
__device__ uint32_t g_aloN[(size_t)NN_NODES*CN/2];
__device__ uint32_t g_ahiE[(size_t)NE_NODES*CE/2];
__device__ uint32_t g_aloE[(size_t)NE_NODES*CE/2];
__device__ uint32_t g_ahiE2[(size_t)NE_NODES*CE/2];
__device__ uint32_t g_aloE2[(size_t)NE_NODES*CE/2];
__device__ uint32_t g_wthi[W_TOT];
__device__ uint32_t g_wtlo[W_TOT];

// precomputed CSR (packed adj: (src_local<<16)|edge_local)
__device__ int g_offE[(size_t)BGR * (MPG + 1)];
__device__ int g_adjE[(size_t)NE_EDGES];
__device__ int g_offN[(size_t)BGR * (NPG + 1)];
__device__ int g_adjN[(size_t)NN_EDGES];

// ---------------------------------------------------------------------------
// split helpers
// ---------------------------------------------------------------------------
__device__ __forceinline__ uint32_t pack_hi(float x, float y, float& rx, float& ry) {
    __nv_bfloat16 hx = __float2bfloat16(x), hy = __float2bfloat16(y);
    rx = x - __bfloat162float(hx);
    ry = y - __bfloat162float(hy);
    return (uint32_t)__bfloat16_as_ushort(hx) | ((uint32_t)__bfloat16_as_ushort(hy) << 16);
}
__device__ __forceinline__ uint32_t pack_lo(float rx, float ry) {
    __nv_bfloat16 lx = __float2bfloat16(rx), ly = __float2bfloat16(ry);
    return (uint32_t)__bfloat16_as_ushort(lx) | ((uint32_t)__bfloat16_as_ushort(ly) << 16);
}
__device__ __forceinline__ void split4(float4 v, uint2& hi, uint2& lo) {
    float r0, r1, r2, r3;
    hi.x = pack_hi(v.x, v.y, r0, r1);
    hi.y = pack_hi(v.z, v.w, r2, r3);
    lo.x = pack_lo(r0, r1);
    lo.y = pack_lo(r2, r3);
}

__global__ void split_bf16(const float2* __restrict__ a, uint32_t* __restrict__ hi,
                           uint32_t* __restrict__ lo, int n2) {
    int i = blockIdx.x * blockDim.x + threadIdx.x;
    if (i >= n2) return;
    float2 v = a[i];
    float rx, ry;
    hi[i] = pack_hi(v.x, v.y, rx, ry);
    lo[i] = pack_lo(rx, ry);
}

// All 8 weight matrices split in one launch, segmented layout.
__global__ void wsplit_all(
    const float* __restrict__ WqE1, const float* __restrict__ WkE1, const float* __restrict__ WvE1,
    const float* __restrict__ WqE2, const float* __restrict__ WkE2, const float* __restrict__ WvE2,
    const float* __restrict__ We1,  const float* __restrict__ We2,
    const float* __restrict__ Wq1,  const float* __restrict__ Wk1,  const float* __restrict__ Wv1,
    const float* __restrict__ Wq2,  const float* __restrict__ Wk2,  const float* __restrict__ Wv2,
    uint32_t* __restrict__ hi, uint32_t* __restrict__ lo)
{
    int i = blockIdx.x * blockDim.x + threadIdx.x;
    if (i >= W_TOT) return;
    const float* W; int Nper, n, kp;
    if (i < W_WE1) {
        int l = i / 6144, r = i % 6144;
        int mat = r / 2048, rr = r % 2048;
        n = rr / 32; kp = rr % 32; Nper = 64;
        const float* tab[6] = {WqE1, WkE1, WvE1, WqE2, WkE2, WvE2};
        W = tab[l * 3 + mat];
    } else if (i < W_N1) {
        int r = i - W_WE1;
        int l = r / 8192; r %= 8192;
        n = r / 32; kp = r % 32; Nper = 256;
        W = l ? We2 : We1;
    } else {
        int r = i - W_N1;
        int l = r / 98304; r %= 98304;
        int mat = r / 32768, rr = r % 32768;
        n = rr / 128; kp = rr % 128; Nper = 256;
        const float* tab[6] = {Wq1, Wk1, Wv1, Wq2, Wk2, Wv2};
        W = tab[l * 3 + mat];
    }
    float vx = W[(size_t)(2 * kp) * Nper + n];
    float vy = W[(size_t)(2 * kp + 1) * Nper + n];
    float rx, ry;
    hi[i] = pack_hi(vx, vy, rx, ry);
    lo[i] = pack_lo(rx, ry);
}

// ---------------------------------------------------------------------------
// CSR build (once per side): block per graph, packed adj
// ---------------------------------------------------------------------------
template <int NODES, int EDGES>
__global__ void csr_build(const int* __restrict__ src, const int* __restrict__ dst,
                          int* __restrict__ gOff, int* __restrict__ gAdj) {
    __shared__ int sOff[NODES + 1];
    __shared__ int sCur[NODES];
    const int g = blockIdx.x, t = threadIdx.x;
    const int nb = g * NODES, eb = g * EDGES;
    for (int i = t; i < NODES; i += 256) sCur[i] = 0;
    __syncthreads();
    for (int e = t; e < EDGES; e += 256) atomicAdd(&sCur[dst[eb + e] - nb], 1);
    __syncthreads();
    if (t == 0) {
        int run = 0;
        for (int i = 0; i < NODES; i++) { sOff[i] = run; run += sCur[i]; }
        sOff[NODES] = run;
    }
    __syncthreads();
    for (int i = t; i < NODES; i += 256) sCur[i] = sOff[i];
    __syncthreads();
    for (int e = t; e < EDGES; e += 256) {
        int d = dst[eb + e] - nb;
        int pos = atomicAdd(&sCur[d], 1);
        gAdj[eb + pos] = ((src[eb + e] - nb) << 16) | e;
    }
    for (int i = t; i < NODES + 1; i += 256) gOff[g * (NODES + 1) + i] = sOff[i];
}

// ---------------------------------------------------------------------------
// mma.sync + ldmatrix + cp.async
// ---------------------------------------------------------------------------
__device__ __forceinline__ void mma_bf16(float* c, const uint32_t* a,
                                         uint32_t b0, uint32_t b1) {
    asm volatile(
        "mma.sync.aligned.m16n8k16.row.col.f32.bf16.bf16.f32 "
        "{%0,%1,%2,%3}, {%4,%5,%6,%7}, {%8,%9}, {%0,%1,%2,%3};"
        : "+f"(c[0]), "+f"(c[1]), "+f"(c[2]), "+f"(c[3])
        : "r"(a[0]), "r"(a[1]), "r"(a[2]), "r"(a[3]), "r"(b0), "r"(b1));
}

__device__ __forceinline__ void ldsm_x4(uint32_t& r0, uint32_t& r1,
                                        uint32_t& r2, uint32_t& r3, uint32_t addr) {
    asm volatile("ldmatrix.sync.aligned.m8n8.x4.shared.b16 {%0,%1,%2,%3}, [%4];"
                 : "=r"(r0), "=r"(r1), "=r"(r2), "=r"(r3) : "r"(addr));
}

__device__ __forceinline__ uint32_t smem_u32(const void* p) {
    uint32_t a;
    asm("{ .reg .u64 t; cvta.to.shared.u64 t, %1; cvt.u32.u64 %0, t; }" : "=r"(a) : "l"(p));
    return a;
}

__device__ __forceinline__ void cp_async16(uint32_t saddr, const void* g) {
    asm volatile("cp.async.cg.shared.global [%0], [%1], 16;" :: "r"(saddr), "l"(g));
}
__device__ __forceinline__ void cp_commit() {
    asm volatile("cp.async.commit_group;" ::: "memory");
}
template<int N>
__device__ __forceinline__ void cp_wait() {
    asm volatile("cp.async.wait_group %0;" :: "n"(N) : "memory");
}

// ---------------------------------------------------------------------------
// HMMA split-bf16 GEMM: cp.async double-buffered pipeline (proven R11-R13).
// ---------------------------------------------------------------------------
template<int WM, int NWN>
__global__ void __launch_bounds__(256) hmma_gemm(
    const uint32_t* __restrict__ ahi, const uint32_t* __restrict__ alo,
    const uint32_t* __restrict__ bhi, const uint32_t* __restrict__ blo,
    float* __restrict__ C0, float* __restrict__ C1, float* __restrict__ C2,
    int M, int K, int Nper, int matdiv)
{
    constexpr int BN  = NWN * 64;
    constexpr int NWM = 8 / NWN;
    constexpr int BM  = NWM * WM * 16;
    constexpr int BUFSZ = (2 * BM + 2 * BN) * 20;
    const int K2 = K >> 1;

    extern __shared__ uint32_t sm[];
    const uint32_t smb = smem_u32(sm);

    const int t = threadIdx.x, warp = t >> 5, lane = t & 31;
    const int mat     = blockIdx.x / matdiv;
    const int colbase = (blockIdx.x % matdiv) * BN;
    const int bm = blockIdx.y * BM;
    const int wm = (warp % NWM) * WM * 16;
    const int wn = (warp / NWM) * 64;
    const int g4 = lane >> 2, t4 = lane & 3;

    const int aRow = (lane & 7) + ((lane >> 3) & 1) * 8;
    const int aKof = (lane >> 4) * 4;
    const int bRow = (lane & 7) + (lane >> 4) * 8;
    const int bKof = ((lane >> 3) & 1) * 4;

    const int brow_base = mat * Nper + colbase;

    auto stage = [&](int kc, int buf) {
        uint32_t base = smb + (uint32_t)buf * BUFSZ * 4;
        for (int idx = t; idx < BM * 4; idx += 256) {
            int r = idx >> 2, q = idx & 3;
            size_t gi = (size_t)(bm + r) * K2 + kc * 16 + q * 4;
            uint32_t so = (uint32_t)(r * 20 + q * 4) * 4;
            cp_async16(base + so, ahi + gi);
            cp_async16(base + (uint32_t)(BM * 20) * 4 + so, alo + gi);
        }
        for (int idx = t; idx < BN * 4; idx += 256) {
            int r = idx >> 2, q = idx & 3;
            size_t gi = (size_t)(brow_base + r) * K2 + kc * 16 + q * 4;
            uint32_t so = (uint32_t)(r * 20 + q * 4) * 4;
            cp_async16(base + (uint32_t)(2 * BM * 20) * 4 + so, bhi + gi);
            cp_async16(base + (uint32_t)((2 * BM + BN) * 20) * 4 + so, blo + gi);
        }
    };

    float acc[WM][8][4];
#pragma unroll
    for (int i = 0; i < WM; i++)
#pragma unroll
        for (int j = 0; j < 8; j++)
#pragma unroll
            for (int q = 0; q < 4; q++) acc[i][j][q] = 0.f;

    const int nch = K2 / 16;
    stage(0, 0);
    cp_commit();

    int buf = 0;
    for (int kc = 0; kc < nch; kc++) {
        if (kc + 1 < nch) {
            stage(kc + 1, buf ^ 1);
            cp_commit();
            cp_wait<1>();
        } else {
            cp_wait<0>();
        }
        __syncthreads();

        uint32_t base = smb + (uint32_t)buf * BUFSZ * 4;
        const uint32_t sAh = base;
        const uint32_t sAl = base + (uint32_t)(BM * 20) * 4;
        const uint32_t sBh = base + (uint32_t)(2 * BM * 20) * 4;
        const uint32_t sBl = base + (uint32_t)((2 * BM + BN) * 20) * 4;

#pragma unroll
        for (int ks = 0; ks < 2; ks++) {
            uint32_t afh[WM][4], afl[WM][4];
#pragma unroll
            for (int i = 0; i < WM; i++) {
                uint32_t off = ((uint32_t)((wm + i * 16 + aRow) * 20 + ks * 8 + aKof)) * 4;
                ldsm_x4(afh[i][0], afh[i][1], afh[i][2], afh[i][3], sAh + off);
                ldsm_x4(afl[i][0], afl[i][1], afl[i][2], afl[i][3], sAl + off);
            }
#pragma unroll
            for (int jp = 0; jp < 4; jp++) {
                uint32_t off = ((uint32_t)((wn + jp * 16 + bRow) * 20 + ks * 8 + bKof)) * 4;
                uint32_t bh0, bh1, bh2, bh3, bl0, bl1, bl2, bl3;
                ldsm_x4(bh0, bh1, bh2, bh3, sBh + off);
                ldsm_x4(bl0, bl1, bl2, bl3, sBl + off);
#pragma unroll
                for (int i = 0; i < WM; i++) {
                    mma_bf16(acc[i][2 * jp],     afh[i], bh0, bh1);
                    mma_bf16(acc[i][2 * jp],     afh[i], bl0, bl1);
                    mma_bf16(acc[i][2 * jp],     afl[i], bh0, bh1);
                    mma_bf16(acc[i][2 * jp + 1], afh[i], bh2, bh3);
                    mma_bf16(acc[i][2 * jp + 1], afh[i], bl2, bl3);
                    mma_bf16(acc[i][2 * jp + 1], afl[i], bh2, bh3);
                }
            }
        }
        __syncthreads();
        buf ^= 1;
    }

    float* __restrict__ Cout = (mat == 0) ? C0 : (mat == 1) ? C1 : C2;
#pragma unroll
    for (int i = 0; i < WM; i++) {
        int r0 = bm + wm + i * 16 + g4;
#pragma unroll
        for (int j = 0; j < 8; j++) {
            int c = colbase + wn + j * 8 + 2 * t4;
            float2 v0 = {acc[i][j][0], acc[i][j][1]};
            float2 v1 = {acc[i][j][2], acc[i][j][3]};
            *(float2*)&Cout[(size_t)r0 * Nper + c]       = v0;
            *(float2*)&Cout[(size_t)(r0 + 8) * Nper + c] = v1;
        }
    }
}

// ---------------------------------------------------------------------------
// ef row mapping (N-side)
// ---------------------------------------------------------------------------
__device__ __forceinline__ const float* ef_row(const float* __restrict__ efbr,
                                               const float* __restrict__ we0,
                                               int g, int e) {
    if (e < 2 * CNUM)       return efbr + ((size_t)g * MPG + (e >> 1)) * CN;
    if (e < 2 * CNUM + NPG) return we0;
    return efbr + ((size_t)g * MPG + e - (CNUM + NPG)) * CN;
}

// ---------------------------------------------------------------------------
// Fused attention conv: precomputed packed CSR, small static smem (R12 shape).
// ---------------------------------------------------------------------------
template <int C, int H, int NODES, int EDGES, bool HAS_EF>
__global__ void __launch_bounds__(256) attn_conv(
    const float* __restrict__ q, const float* __restrict__ k,
    const float* __restrict__ v,
    const float* __restrict__ efbr, const float* __restrict__ we0,
    const int* __restrict__ gOff, const int* __restrict__ gAdj,
    float* __restrict__ outbuf, float* __restrict__ bnpart, float scale)
{
    constexpr int Oh = C / H;
    constexpr int WA = Oh / 8;
    constexpr int WB = C / 32;

    __shared__ int   sOff[NODES + 1];
    __shared__ int   sAdj[EDGES];
    __shared__ float sW[EDGES * H];
    __shared__ float sSumW[8 * H];
    __shared__ float sBN[2 * C];

    const int g = blockIdx.x, t = threadIdx.x;
    const int nb = g * NODES, eb = g * EDGES;
    const int warp = t >> 5, lane = t & 31;

    for (int i = t; i < NODES + 1; i += 256) sOff[i] = gOff[g * (NODES + 1) + i];
    for (int i = t; i < EDGES; i += 256) sAdj[i] = gAdj[eb + i];
    for (int i = t; i < 2 * C; i += 256) sBN[i] = 0.f;
    __syncthreads();

    const int h = lane >> 3, u = lane & 7;
    const int cA = h * Oh + u * WA;
    const int cB = lane * WB;
    const int headB = cB / Oh;

    float s1[WB], s2[WB];
#pragma unroll
    for (int j = 0; j < WB; j++) { s1[j] = 0.f; s2[j] = 0.f; }

    for (int d = warp; d < NODES; d += 8) {
        const int e0 = sOff[d], e1 = sOff[d + 1];

        float qv[WA];
        {
            const float* qr = q + (size_t)(nb + d) * C + cA;
            if constexpr (WA == 8) {
                float4 a = *(const float4*)qr, b = *(const float4*)(qr + 4);
                qv[0] = a.x; qv[1] = a.y; qv[2] = a.z; qv[3] = a.w;
                qv[4] = b.x; qv[5] = b.y; qv[6] = b.z; qv[7] = b.w;
            } else {
                float2 a = *(const float2*)qr;
                qv[0] = a.x; qv[1] = a.y;
            }
        }

        // ---- phase 1: logits + max ----
        float mx = -INFINITY;
        for (int ii = e0; ii < e1; ii++) {
            int pk = sAdj[ii];
            int e = pk & 0xffff, s = pk >> 16;
            const float* kr = k + (size_t)(nb + s) * C + cA;
            float kk[WA];
            if constexpr (WA == 8) {
                float4 a = *(const float4*)kr, b = *(const float4*)(kr + 4);
                kk[0] = a.x; kk[1] = a.y; kk[2] = a.z; kk[3] = a.w;
                kk[4] = b.x; kk[5] = b.y; kk[6] = b.z; kk[7] = b.w;
            } else {
                float2 a = *(const float2*)kr;
                kk[0] = a.x; kk[1] = a.y;
            }
            if (HAS_EF) {
                const float* er = ef_row(efbr, we0, g, e) + cA;
                if constexpr (WA == 8) {
                    float4 a = *(const float4*)er, b = *(const float4*)(er + 4);
                    kk[0] += a.x; kk[1] += a.y; kk[2] += a.z; kk[3] += a.w;
                    kk[4] += b.x; kk[5] += b.y; kk[6] += b.z; kk[7] += b.w;
                } else {
                    float2 a = *(const float2*)er;
                    kk[0] += a.x; kk[1] += a.y;
                }
            }
            float p = 0.f;
#pragma unroll
            for (int j = 0; j < WA; j++) p += qv[j] * kk[j];
            p += __shfl_xor_sync(0xffffffffu, p, 1);
            p += __shfl_xor_sync(0xffffffffu, p, 2);
            p += __shfl_xor_sync(0xffffffffu, p, 4);
            float l = p * scale;
            l = (l > 0.f) ? l : 0.2f * l;
            if (u == 0) sW[e * H + h] = l;
            mx = fmaxf(mx, l);
        }
        __syncwarp();

        // ---- phase 2: weights + per-head sum ----
        float sumh = 0.f;
        for (int ii = e0; ii < e1; ii++) {
            int e = sAdj[ii] & 0xffff;
            float w = expf(sW[e * H + h] - mx);
            if (u == 0) sW[e * H + h] = w;
            sumh += w;
        }
        if (u == 0) sSumW[warp * H + h] = sumh;
        __syncwarp();

        // ---- phase 3: accumulate w * (v + ef) ----
        float acc[WB];
#pragma unroll
        for (int j = 0; j < WB; j++) acc[j] = 0.f;
        for (int ii = e0; ii < e1; ii++) {
            int pk = sAdj[ii];
            int e = pk & 0xffff, s = pk >> 16;
            const float w = sW[e * H + headB];
            const float* vr = v + (size_t)(nb + s) * C + cB;
            float vv[WB];
            if constexpr (WB == 8) {
                float4 a = *(const float4*)vr, b = *(const float4*)(vr + 4);
                vv[0] = a.x; vv[1] = a.y; vv[2] = a.z; vv[3] = a.w;
                vv[4] = b.x; vv[5] = b.y; vv[6] = b.z; vv[7] = b.w;
            } else {
                float2 a = *(const float2*)vr;
                vv[0] = a.x; vv[1] = a.y;
            }
            if (HAS_EF) {
                const float* er = ef_row(efbr, we0, g, e) + cB;
                if constexpr (WB == 8) {
                    float4 a = *(const float4*)er, b = *(const float4*)(er + 4);
                    vv[0] += a.x; vv[1] += a.y; vv[2] += a.z; vv[3] += a.w;
                    vv[4] += b.x; vv[5] += b.y; vv[6] += b.z; vv[7] += b.w;
                } else {
                    float2 a = *(const float2*)er;
                    vv[0] += a.x; vv[1] += a.y;
                }
            }
#pragma unroll
            for (int j = 0; j < WB; j++) acc[j] += w * vv[j];
        }

        // ---- phase 4: normalize + write + BN partials ----
        const float denom = sSumW[warp * H + headB] + 1e-16f;
        float* orow = outbuf + (size_t)(nb + d) * C + cB;
        float o[WB];
#pragma unroll
        for (int j = 0; j < WB; j++) {
            o[j] = acc[j] / denom;
            s1[j] += o[j]; s2[j] += o[j] * o[j];
        }
        if constexpr (WB == 8) {
            *(float4*)orow       = make_float4(o[0], o[1], o[2], o[3]);
            *(float4*)(orow + 4) = make_float4(o[4], o[5], o[6], o[7]);
        } else {
            *(float2*)orow = make_float2(o[0], o[1]);
        }
    }

#pragma unroll
    for (int j = 0; j < WB; j++) {
        atomicAdd(&sBN[cB + j], s1[j]);
        atomicAdd(&sBN[C + cB + j], s2[j]);
    }
    __syncthreads();
    for (int i = t; i < 2 * C; i += 256)
        bnpart[(size_t)g * 2 * C + i] = sBN[i];
}

// ---------------------------------------------------------------------------
// BN stats reduce, parallel over channels (grid = C)
// ---------------------------------------------------------------------------
template <int C>
__global__ void bn_final3(const float* __restrict__ part,
                          float* __restrict__ mu, float* __restrict__ rstd,
                          int nblocks, int Nrows) {
    __shared__ float rs[256], rss[256];
    int c = blockIdx.x, t = threadIdx.x;
    float s = 0.f, ss = 0.f;
    for (int b = t; b < nblocks; b += 256) {
        s  += part[(size_t)b * 2 * C + c];
        ss += part[(size_t)b * 2 * C + C + c];
    }
    rs[t] = s; rss[t] = ss;
    __syncthreads();
    for (int o = 128; o > 0; o >>= 1) {
        if (t < o) { rs[t] += rs[t + o]; rss[t] += rss[t + o]; }
        __syncthreads();
    }
    if (t == 0) {
        float m = rs[0] / (float)Nrows;
        float v = rss[0] / (float)Nrows - m * m;
        mu[c] = m;
        rstd[c] = rsqrtf(v + 1e-5f);
    }
}

// ---------------------------------------------------------------------------
// BN apply variants (float4), with fused bf16 split outputs
// ---------------------------------------------------------------------------
template <int C, bool SUB>
__global__ void bn_apply4s(const float4* __restrict__ o, const float4* __restrict__ res,
                           const float* __restrict__ mu, const float* __restrict__ rstd,
                           const float* __restrict__ g, const float* __restrict__ b,
                           float4* __restrict__ out,
                           uint2* __restrict__ shi, uint2* __restrict__ slo, int n4) {
    int i = blockIdx.x * blockDim.x + threadIdx.x;
    if (i >= n4) return;
    int c = (i % (C / 4)) * 4;
    float4 ov = o[i], rv = res[i], y;
    y.x = fmaxf((ov.x - mu[c+0]) * rstd[c+0] * g[c+0] + b[c+0], 0.f);
    y.y = fmaxf((ov.y - mu[c+1]) * rstd[c+1] * g[c+1] + b[c+1], 0.f);
    y.z = fmaxf((ov.z - mu[c+2]) * rstd[c+2] * g[c+2] + b[c+2], 0.f);
    y.w = fmaxf((ov.w - mu[c+3]) * rstd[c+3] * g[c+3] + b[c+3], 0.f);
    float4 r;
    if (SUB) { r.x = rv.x - y.x; r.y = rv.y - y.y; r.z = rv.z - y.z; r.w = rv.w - y.w; }
    else     { r.x = rv.x + y.x; r.y = rv.y + y.y; r.z = rv.z + y.z; r.w = rv.w + y.w; }
    out[i] = r;
    uint2 hi, lo;
    split4(r, hi, lo);
    shi[i] = hi; slo[i] = lo;
}

__global__ void bn_apply_toedge4(const float4* __restrict__ o, const float4* __restrict__ res,
                                 const float* __restrict__ mu, const float* __restrict__ rstd,
                                 const float* __restrict__ gg, const float* __restrict__ bb,
                                 float4* __restrict__ brout, float4* __restrict__ ei,
                                 uint2* __restrict__ shi, uint2* __restrict__ slo) {
    int i = blockIdx.x * blockDim.x + threadIdx.x;
    if (i >= NE_NODES * (CE / 4)) return;
    int c4 = i & 15, c = c4 * 4;
    int row = i >> 4;
    int g = row >> 7, r = row & 127;
    float4 ov = o[i], rv = res[i], val;
    val.x = rv.x - fmaxf((ov.x - mu[c+0]) * rstd[c+0] * gg[c+0] + bb[c+0], 0.f);
    val.y = rv.y - fmaxf((ov.y - mu[c+1]) * rstd[c+1] * gg[c+1] + bb[c+1], 0.f);
    val.z = rv.z - fmaxf((ov.z - mu[c+2]) * rstd[c+2] * gg[c+2] + bb[c+2], 0.f);
    val.w = rv.w - fmaxf((ov.w - mu[c+3]) * rstd[c+3] * gg[c+3] + bb[c+3], 0.f);
    brout[i] = val;
    uint2 hi, lo;
    split4(val, hi, lo);
    shi[i] = hi; slo[i] = lo;
    size_t eib = (size_t)g * EPG;
    if (r < CNUM) {
        ei[(eib + 2 * r) * 16 + c4]     = val;
        ei[(eib + 2 * r + 1) * 16 + c4] = val;
    } else {
        ei[(eib + r + (CNUM + NPG)) * 16 + c4] = val;
    }
}

__global__ void bn_apply_sn4(const float4* __restrict__ o, const float4* __restrict__ res,
                             const float* __restrict__ mu, const float* __restrict__ rstd,
                             const float* __restrict__ gg, const float* __restrict__ bb,
                             float4* __restrict__ out, float4* __restrict__ sn) {
    int i = blockIdx.x * blockDim.x + threadIdx.x;
    if (i >= NN_NODES * (CN / 4)) return;
    int c4 = i & 63, c = c4 * 4;
    int row = i >> 6;
    float4 ov = o[i], rv = res[i], val;
    val.x = rv.x - fmaxf((ov.x - mu[c+0]) * rstd[c+0] * gg[c+0] + bb[c+0], 0.f);
    val.y = rv.y - fmaxf((ov.y - mu[c+1]) * rstd[c+1] * gg[c+1] + bb[c+1], 0.f);
    val.z = rv.z - fmaxf((ov.z - mu[c+2]) * rstd[c+2] * gg[c+2] + bb[c+2], 0.f);
    val.w = rv.w - fmaxf((ov.w - mu[c+3]) * rstd[c+3] * gg[c+3] + bb[c+3], 0.f);
    out[i] = val;
    if ((row & 63) == 63) sn[(size_t)(row >> 6) * 64 + c4] = val;
}

__global__ void onehot_fill(float* __restrict__ ei) {
    int i = blockIdx.x * blockDim.x + threadIdx.x;
    if (i >= BGR * NPG * CE) return;
    int c = i % CE;
    int row = i / CE;
    int g = row / NPG, rr = row % NPG;
    ei[((size_t)g * EPG + 2 * CNUM + rr) * CE + c] = (c == 0) ? 1.f : 0.f;
}

// ---------------------------------------------------------------------------
// Host orchestration (two streams, event fork/join)
// ---------------------------------------------------------------------------
static inline float* sym(const void* s) {
    void* p = nullptr;
    cudaGetSymbolAddress(&p, (const void*)s);
    return (float*)p;
}

static cudaStream_t make_stream() {
    cudaStream_t s;
    cudaStreamCreateWithFlags(&s, cudaStreamNonBlocking);
    return s;
}
static cudaEvent_t make_event() {
    cudaEvent_t e;
    cudaEventCreateWithFlags(&e, cudaEventDisableTiming);
    return e;
}

extern "C" void kernel_launch(void* const* d_in, const int* in_sizes, int n_in,
                              void* d_out, int out_size) {
    (void)in_sizes; (void)n_in; (void)out_size;
    const float* x    = (const float*)d_in[0];
    const int*   eiN  = (const int*)d_in[1];
    const float* brf  = (const float*)d_in[2];
    const int*   eiE  = (const int*)d_in[3];
    const float* WqE1 = (const float*)d_in[4];
    const float* WkE1 = (const float*)d_in[5];
    const float* WvE1 = (const float*)d_in[6];
    const float* gE1  = (const float*)d_in[7];
    const float* bE1  = (const float*)d_in[8];
    const float* Wq1  = (const float*)d_in[9];
    const float* Wk1  = (const float*)d_in[10];
    const float* Wv1  = (const float*)d_in[11];
    const float* We1  = (const float*)d_in[12];
    const float* gN1  = (const float*)d_in[13];
    const float* bN1  = (const float*)d_in[14];
    const float* WqE2 = (const float*)d_in[15];
    const float* WkE2 = (const float*)d_in[16];
    const float* WvE2 = (const float*)d_in[17];
    const float* gE2  = (const float*)d_in[18];
    const float* bE2  = (const float*)d_in[19];
    const float* Wq2  = (const float*)d_in[20];
    const float* Wk2  = (const float*)d_in[21];
    const float* Wv2  = (const float*)d_in[22];
    const float* We2  = (const float*)d_in[23];
    const float* gN2  = (const float*)d_in[24];
    const float* bN2  = (const float*)d_in[25];

    float* out = (float*)d_out;
    float* out2_buf = out + OFF_OUT2;
    float* ei2_buf  = out + OFF_EI;
    float* br2_buf  = out + OFF_BR;
    float* sn_buf   = out + OFF_SN;

    float* qE   = sym(g_qE);   float* kE   = sym(g_kE);   float* vE  = sym(g_vE);
    float* accE = sym(g_accE); float* br1  = sym(g_br1);
    float* efbr = sym(g_efbr); float* efbr2 = sym(g_efbr2);
    float* qN   = sym(g_qN);   float* kN   = sym(g_kN);   float* vN  = sym(g_vN);
    float* accN = sym(g_accN); float* out1 = sym(g_out1);
    float* bnpartE = sym(g_bnpartE); float* bnpartN = sym(g_bnpartN);
    float* muE = sym(g_muE); float* rstdE = sym(g_rstdE);
    float* muN = sym(g_muN); float* rstdN = sym(g_rstdN);
    uint32_t* ahiN = (uint32_t*)sym(g_ahiN); uint32_t* aloN = (uint32_t*)sym(g_aloN);
    uint32_t* ahiE = (uint32_t*)sym(g_ahiE); uint32_t* aloE = (uint32_t*)sym(g_aloE);
    uint32_t* ahiE2 = (uint32_t*)sym(g_ahiE2); uint32_t* aloE2 = (uint32_t*)sym(g_aloE2);
    uint32_t* whi = (uint32_t*)sym(g_wthi); uint32_t* wlo = (uint32_t*)sym(g_wtlo);
    int* offE = (int*)sym(g_offE); int* adjE = (int*)sym(g_adjE);
    int* offN = (int*)sym(g_offN); int* adjN = (int*)sym(g_adjN);

    const int* srcE = eiE;              const int* dstE = eiE + NE_EDGES;
    const int* srcN = eiN;              const int* dstN = eiN + NN_EDGES;

    const float scaleE = 0.25f;
    const float scaleN = 0.125f;

    const int nE2 = NE_NODES * CE / 2;
    const int nN2 = NN_NODES * CN / 2;
    const int nE4 = NE_NODES * CE / 4;
    const int nN4 = NN_NODES * CN / 4;

    const int SME = 2 * (2 * 256 + 2 * 64) * 20 * 4;    // 102400
    const int SMN = 2 * (2 * 128 + 2 * 128) * 20 * 4;   // 81920
    cudaFuncSetAttribute(hmma_gemm<2, 1>, cudaFuncAttributeMaxDynamicSharedMemorySize, SME);
    cudaFuncSetAttribute(hmma_gemm<2, 2>, cudaFuncAttributeMaxDynamicSharedMemorySize, SMN);

    static cudaStream_t s2 = make_stream();
    static cudaEvent_t evW   = make_event();
    static cudaEvent_t evQN1 = make_event();
    static cudaEvent_t evBr1 = make_event();
    static cudaEvent_t evEf2 = make_event();

    // ===== main: CSR + weights + constants + brf split =====
    csr_build<MPG, MPG * 4><<<BGR, 256>>>(srcE, dstE, offE, adjE);
    csr_build<NPG, EPG><<<BGR, 256>>>(srcN, dstN, offN, adjN);
    wsplit_all<<<(W_TOT + 255) / 256, 256>>>(WqE1, WkE1, WvE1, WqE2, WkE2, WvE2,
                                             We1, We2, Wq1, Wk1, Wv1, Wq2, Wk2, Wv2,
                                             whi, wlo);
    onehot_fill<<<(BGR * NPG * CE) / 256, 256>>>(ei2_buf);
    split_bf16<<<(nE2 + 255) / 256, 256>>>((const float2*)brf, ahiE, aloE, nE2);
    cudaEventRecord(evW, 0);
    cudaStreamWaitEvent(s2, evW, 0);

    // ===== stream2: N1 prep =====
    split_bf16<<<(nN2 + 255) / 256, 256, 0, s2>>>((const float2*)x, ahiN, aloN, nN2);
    hmma_gemm<2, 2><<<dim3(6, NN_NODES / 128), 256, SMN, s2>>>(
        ahiN, aloN, whi + W_N1, wlo + W_N1, qN, kN, vN, NN_NODES, CN, 256, 2);
    cudaEventRecord(evQN1, s2);

    // ===== main: E1 chain =====
    hmma_gemm<2, 1><<<dim3(3, NE_NODES / 256), 256, SME>>>(
        ahiE, aloE, whi + W_E1, wlo + W_E1, qE, kE, vE, NE_NODES, CE, 64, 1);
    attn_conv<CE, 4, MPG, MPG * 4, false><<<BGR, 256>>>(
        qE, kE, vE, nullptr, nullptr, offE, adjE, accE, bnpartE, scaleE);
    bn_final3<CE><<<CE, 256>>>(bnpartE, muE, rstdE, BGR, NE_NODES);
    bn_apply4s<CE, false><<<nE4 / 256, 256>>>(
        (const float4*)accE, (const float4*)brf, muE, rstdE, gE1, bE1,
        (float4*)br1, (uint2*)ahiE, (uint2*)aloE, nE4);
    cudaEventRecord(evBr1, 0);
    cudaStreamWaitEvent(s2, evBr1, 0);

    // ===== main: ef1 + N1 attn chain =====
    hmma_gemm<2, 2><<<dim3(2, NE_NODES / 128), 256, SMN>>>(
        ahiE, aloE, whi + W_WE1, wlo + W_WE1, efbr, efbr, efbr, NE_NODES, CE, 256, 2);
    cudaStreamWaitEvent(0, evQN1, 0);
    attn_conv<CN, 4, NPG, EPG, true><<<BGR, 256>>>(
        qN, kN, vN, efbr, We1, offN, adjN, accN, bnpartN, scaleN);
    bn_final3<CN><<<CN, 256>>>(bnpartN, muN, rstdN, BGR, NN_NODES);
    bn_apply4s<CN, false><<<nN4 / 256, 256>>>(
        (const float4*)accN, (const float4*)x, muN, rstdN, gN1, bN1,
        (float4*)out1, (uint2*)ahiN, (uint2*)aloN, nN4);

    // ===== stream2: E2 chain =====
    hmma_gemm<2, 1><<<dim3(3, NE_NODES / 256), 256, SME, s2>>>(
        ahiE, aloE, whi + W_E2, wlo + W_E2, qE, kE, vE, NE_NODES, CE, 64, 1);
    attn_conv<CE, 4, MPG, MPG * 4, false><<<BGR, 256, 0, s2>>>(
        qE, kE, vE, nullptr, nullptr, offE, adjE, accE, bnpartE, scaleE);
    bn_final3<CE><<<CE, 256, 0, s2>>>(bnpartE, muE, rstdE, BGR, NE_NODES);
    bn_apply_toedge4<<<nE4 / 256, 256, 0, s2>>>(
        (const float4*)accE, (const float4*)br1, muE, rstdE, gE2, bE2,
        (float4*)br2_buf, (float4*)ei2_buf, (uint2*)ahiE2, (uint2*)aloE2);
    hmma_gemm<2, 2><<<dim3(2, NE_NODES / 128), 256, SMN, s2>>>(
        ahiE2, aloE2, whi + W_WE2, wlo + W_WE2, efbr2, efbr2, efbr2, NE_NODES, CE, 256, 2);
    cudaEventRecord(evEf2, s2);

    // ===== main: N2 chain =====
    hmma_gemm<2, 2><<<dim3(6, NN_NODES / 128), 256, SMN>>>(
        ahiN, aloN, whi + W_N2, wlo + W_N2, qN, kN, vN, NN_NODES, CN, 256, 2);
    cudaStreamWaitEvent(0, evEf2, 0);
    attn_conv<CN, 4, NPG, EPG, true><<<BGR, 256>>>(
        qN, kN, vN, efbr2, We2, offN, adjN, accN, bnpartN, scaleN);
    bn_final3<CN><<<CN, 256>>>(bnpartN, muN, rstdN, BGR, NN_NODES);
    bn_apply_sn4<<<nN4 / 256, 256>>>(
        (const float4*)accN, (const float4*)out1, muN, rstdN, gN2, bN2,
        (float4*)out2_buf, (float4*)sn_buf);
}

// round 16
// speedup vs baseline: 1.3184x; 1.2605x over previous
#include <cuda_runtime.h>
#include <cuda_fp16.h>
#include <cstdint>
#include <cstring>
#include <math.h>

// ---------------------------------------------------------------------------
// Problem constants
// ---------------------------------------------------------------------------
#define BGR   512
#define NPG   64
#define CNUM  8
#define MPG   128
#define CN    256
#define CE    64
#define EPG   200

#define NE_NODES (BGR*MPG)        // 65536
#define NE_EDGES (BGR*MPG*4)      // 262144
#define NN_NODES (BGR*NPG)        // 32768
#define NN_EDGES (BGR*EPG)        // 102400

#define OFF_OUT2 0
#define OFF_EI   ((size_t)NN_NODES*CN)
#define OFF_BR   (OFF_EI + (size_t)NN_EDGES*CE)
#define OFF_SN   (OFF_BR + (size_t)NE_NODES*CE)

// weight segment offsets (u32 pair units)
#define W_E1  0
#define W_E2  6144
#define W_WE1 12288
#define W_WE2 20480
#define W_N1  28672
#define W_N2  126976
#define W_TOT 225280

// ---------------------------------------------------------------------------
// Scratch (device globals)
// ---------------------------------------------------------------------------
__device__ float g_qE[(size_t)NE_NODES*CE];
__device__ float g_kE[(size_t)NE_NODES*CE];
__device__ float g_vE[(size_t)NE_NODES*CE];
__device__ float g_accE[(size_t)NE_NODES*CE];
__device__ float g_br1[(size_t)NE_NODES*CE];

__device__ float g_efbr[(size_t)NE_NODES*CN];
__device__ float g_efbr2[(size_t)NE_NODES*CN];
__device__ float g_qN[(size_t)NN_NODES*CN];
__device__ float g_kN[(size_t)NN_NODES*CN];
__device__ float g_vN[(size_t)NN_NODES*CN];
__device__ float g_accN[(size_t)NN_NODES*CN];
__device__ float g_out1[(size_t)NN_NODES*CN];

__device__ float g_bnpartE[(size_t)BGR * 2 * CE];
__device__ float g_bnpartN[(size_t)BGR * 2 * CN];
__device__ float g_muE[CE];
__device__ float g_rstdE[CE];
__device__ float g_muN[CN];
__device__ float g_rstdN[CN];

__device__ uint32_t g_ahiN[(size_t)NN_NODES*CN/2];
__device__ uint32_t g_aloN[(size_t)NN_NODES*CN/2];
__device__ uint32_t g_ahiE[(size_t)NE_NODES*CE/2];
__device__ uint32_t g_aloE[(size_t)NE_NODES*CE/2];
__device__ uint32_t g_ahiE2[(size_t)NE_NODES*CE/2];
__device__ uint32_t g_aloE2[(size_t)NE_NODES*CE/2];
__device__ uint32_t g_wthi[W_TOT];

// precomputed CSR (packed adj: (src_local<<16)|edge_local)
__device__ int g_offE[(size_t)BGR * (MPG + 1)];
__device__ int g_adjE[(size_t)NE_EDGES];
__device__ int g_offN[(size_t)BGR * (NPG + 1)];
__device__ int g_adjN[(size_t)NN_EDGES];

// ---------------------------------------------------------------------------
// fp16 split helpers: activations split hi+lo (exact to ~2^-22),
// weights rounded to fp16 (hi only).
// ---------------------------------------------------------------------------
__device__ __forceinline__ uint32_t pack_hi(float x, float y, float& rx, float& ry) {
    __half hx = __float2half_rn(x), hy = __float2half_rn(y);
    rx = x - __half2float(hx);
    ry = y - __half2float(hy);
    return (uint32_t)__half_as_ushort(hx) | ((uint32_t)__half_as_ushort(hy) << 16);
}
__device__ __forceinline__ uint32_t pack_lo(float rx, float ry) {
    __half lx = __float2half_rn(rx), ly = __float2half_rn(ry);
    return (uint32_t)__half_as_ushort(lx) | ((uint32_t)__half_as_ushort(ly) << 16);
}
__device__ __forceinline__ void split4(float4 v, uint2& hi, uint2& lo) {
    float r0, r1, r2, r3;
    hi.x = pack_hi(v.x, v.y, r0, r1);
    hi.y = pack_hi(v.z, v.w, r2, r3);
    lo.x = pack_lo(r0, r1);
    lo.y = pack_lo(r2, r3);
}

__global__ void split_f16(const float2* __restrict__ a, uint32_t* __restrict__ hi,
                          uint32_t* __restrict__ lo, int n2) {
    int i = blockIdx.x * blockDim.x + threadIdx.x;
    if (i >= n2) return;
    float2 v = a[i];
    float rx, ry;
    hi[i] = pack_hi(v.x, v.y, rx, ry);
    lo[i] = pack_lo(rx, ry);
}

// All 8 weight matrices -> fp16 (hi only), segmented layout.
__global__ void wsplit_all(
    const float* __restrict__ WqE1, const float* __restrict__ WkE1, const float* __restrict__ WvE1,
    const float* __restrict__ WqE2, const float* __restrict__ WkE2, const float* __restrict__ WvE2,
    const float* __restrict__ We1,  const float* __restrict__ We2,
    const float* __restrict__ Wq1,  const float* __restrict__ Wk1,  const float* __restrict__ Wv1,
    const float* __restrict__ Wq2,  const float* __restrict__ Wk2,  const float* __restrict__ Wv2,
    uint32_t* __restrict__ hi)
{
    int i = blockIdx.x * blockDim.x + threadIdx.x;
    if (i >= W_TOT) return;
    const float* W; int Nper, n, kp;
    if (i < W_WE1) {
        int l = i / 6144, r = i % 6144;
        int mat = r / 2048, rr = r % 2048;
        n = rr / 32; kp = rr % 32; Nper = 64;
        const float* tab[6] = {WqE1, WkE1, WvE1, WqE2, WkE2, WvE2};
        W = tab[l * 3 + mat];
    } else if (i < W_N1) {
        int r = i - W_WE1;
        int l = r / 8192; r %= 8192;
        n = r / 32; kp = r % 32; Nper = 256;
        W = l ? We2 : We1;
    } else {
        int r = i - W_N1;
        int l = r / 98304; r %= 98304;
        int mat = r / 32768, rr = r % 32768;
        n = rr / 128; kp = rr % 128; Nper = 256;
        const float* tab[6] = {Wq1, Wk1, Wv1, Wq2, Wk2, Wv2};
        W = tab[l * 3 + mat];
    }
    float vx = W[(size_t)(2 * kp) * Nper + n];
    float vy = W[(size_t)(2 * kp + 1) * Nper + n];
    __half hx = __float2half_rn(vx), hy = __float2half_rn(vy);
    hi[i] = (uint32_t)__half_as_ushort(hx) | ((uint32_t)__half_as_ushort(hy) << 16);
}

// ---------------------------------------------------------------------------
// CSR build (once per side): block per graph, packed adj
// ---------------------------------------------------------------------------
template <int NODES, int EDGES>
__global__ void csr_build(const int* __restrict__ src, const int* __restrict__ dst,
                          int* __restrict__ gOff, int* __restrict__ gAdj) {
    __shared__ int sOff[NODES + 1];
    __shared__ int sCur[NODES];
    const int g = blockIdx.x, t = threadIdx.x;
    const int nb = g * NODES, eb = g * EDGES;
    for (int i = t; i < NODES; i += 256) sCur[i] = 0;
    __syncthreads();
    for (int e = t; e < EDGES; e += 256) atomicAdd(&sCur[dst[eb + e] - nb], 1);
    __syncthreads();
    if (t == 0) {
        int run = 0;
        for (int i = 0; i < NODES; i++) { sOff[i] = run; run += sCur[i]; }
        sOff[NODES] = run;
    }
    __syncthreads();
    for (int i = t; i < NODES; i += 256) sCur[i] = sOff[i];
    __syncthreads();
    for (int e = t; e < EDGES; e += 256) {
        int d = dst[eb + e] - nb;
        int pos = atomicAdd(&sCur[d], 1);
        gAdj[eb + pos] = ((src[eb + e] - nb) << 16) | e;
    }
    for (int i = t; i < NODES + 1; i += 256) gOff[g * (NODES + 1) + i] = sOff[i];
}

// ---------------------------------------------------------------------------
// mma.sync (f16) + ldmatrix + cp.async
// ---------------------------------------------------------------------------
__device__ __forceinline__ void mma_f16(float* c, const uint32_t* a,
                                        uint32_t b0, uint32_t b1) {
    asm volatile(
        "mma.sync.aligned.m16n8k16.row.col.f32.f16.f16.f32 "
        "{%0,%1,%2,%3}, {%4,%5,%6,%7}, {%8,%9}, {%0,%1,%2,%3};"
        : "+f"(c[0]), "+f"(c[1]), "+f"(c[2]), "+f"(c[3])
        : "r"(a[0]), "r"(a[1]), "r"(a[2]), "r"(a[3]), "r"(b0), "r"(b1));
}

__device__ __forceinline__ void ldsm_x4(uint32_t& r0, uint32_t& r1,
                                        uint32_t& r2, uint32_t& r3, uint32_t addr) {
    asm volatile("ldmatrix.sync.aligned.m8n8.x4.shared.b16 {%0,%1,%2,%3}, [%4];"
                 : "=r"(r0), "=r"(r1), "=r"(r2), "=r"(r3) : "r"(addr));
}

__device__ __forceinline__ uint32_t smem_u32(const void* p) {
    uint32_t a;
    asm("{ .reg .u64 t; cvta.to.shared.u64 t, %1; cvt.u32.u64 %0, t; }" : "=r"(a) : "l"(p));
    return a;
}

__device__ __forceinline__ void cp_async16(uint32_t saddr, const void* g) {
    asm volatile("cp.async.cg.shared.global [%0], [%1], 16;" :: "r"(saddr), "l"(g));
}
__device__ __forceinline__ void cp_commit() {
    asm volatile("cp.async.commit_group;" ::: "memory");
}
template<int N>
__device__ __forceinline__ void cp_wait() {
    asm volatile("cp.async.wait_group %0;" :: "n"(N) : "memory");
}

// ---------------------------------------------------------------------------
// HMMA fp16 GEMM, 2-pass (a_hi + a_lo) x fp16(W), cp.async double-buffered.
// C = A @ Wt^T ; A split hi/lo, B hi only.
// ---------------------------------------------------------------------------
template<int WM, int NWN>
__global__ void __launch_bounds__(256) hmma_gemm(
    const uint32_t* __restrict__ ahi, const uint32_t* __restrict__ alo,
    const uint32_t* __restrict__ bhi,
    float* __restrict__ C0, float* __restrict__ C1, float* __restrict__ C2,
    int M, int K, int Nper, int matdiv)
{
    constexpr int BN  = NWN * 64;
    constexpr int NWM = 8 / NWN;
    constexpr int BM  = NWM * WM * 16;
    constexpr int BUFSZ = (2 * BM + BN) * 20;
    const int K2 = K >> 1;

    extern __shared__ uint32_t sm[];
    const uint32_t smb = smem_u32(sm);

    const int t = threadIdx.x, warp = t >> 5, lane = t & 31;
    const int mat     = blockIdx.x / matdiv;
    const int colbase = (blockIdx.x % matdiv) * BN;
    const int bm = blockIdx.y * BM;
    const int wm = (warp % NWM) * WM * 16;
    const int wn = (warp / NWM) * 64;
    const int g4 = lane >> 2, t4 = lane & 3;

    const int aRow = (lane & 7) + ((lane >> 3) & 1) * 8;
    const int aKof = (lane >> 4) * 4;
    const int bRow = (lane & 7) + (lane >> 4) * 8;
    const int bKof = ((lane >> 3) & 1) * 4;

    const int brow_base = mat * Nper + colbase;

    auto stage = [&](int kc, int buf) {
        uint32_t base = smb + (uint32_t)buf * BUFSZ * 4;
        for (int idx = t; idx < BM * 4; idx += 256) {
            int r = idx >> 2, q = idx & 3;
            size_t gi = (size_t)(bm + r) * K2 + kc * 16 + q * 4;
            uint32_t so = (uint32_t)(r * 20 + q * 4) * 4;
            cp_async16(base + so, ahi + gi);
            cp_async16(base + (uint32_t)(BM * 20) * 4 + so, alo + gi);
        }
        for (int idx = t; idx < BN * 4; idx += 256) {
            int r = idx >> 2, q = idx & 3;
            size_t gi = (size_t)(brow_base + r) * K2 + kc * 16 + q * 4;
            uint32_t so = (uint32_t)(r * 20 + q * 4) * 4;
            cp_async16(base + (uint32_t)(2 * BM * 20) * 4 + so, bhi + gi);
        }
    };

    float acc[WM][8][4];
#pragma unroll
    for (int i = 0; i < WM; i++)
#pragma unroll
        for (int j = 0; j < 8; j++)
#pragma unroll
            for (int q = 0; q < 4; q++) acc[i][j][q] = 0.f;

    const int nch = K2 / 16;
    stage(0, 0);
    cp_commit();

    int buf = 0;
    for (int kc = 0; kc < nch; kc++) {
        if (kc + 1 < nch) {
            stage(kc + 1, buf ^ 1);
            cp_commit();
            cp_wait<1>();
        } else {
            cp_wait<0>();
        }
        __syncthreads();

        uint32_t base = smb + (uint32_t)buf * BUFSZ * 4;
        const uint32_t sAh = base;
        const uint32_t sAl = base + (uint32_t)(BM * 20) * 4;
        const uint32_t sBh = base + (uint32_t)(2 * BM * 20) * 4;

#pragma unroll
        for (int ks = 0; ks < 2; ks++) {
            uint32_t afh[WM][4], afl[WM][4];
#pragma unroll
            for (int i = 0; i < WM; i++) {
                uint32_t off = ((uint32_t)((wm + i * 16 + aRow) * 20 + ks * 8 + aKof)) * 4;
                ldsm_x4(afh[i][0], afh[i][1], afh[i][2], afh[i][3], sAh + off);
                ldsm_x4(afl[i][0], afl[i][1], afl[i][2], afl[i][3], sAl + off);
            }
#pragma unroll
            for (int jp = 0; jp < 4; jp++) {
                uint32_t off = ((uint32_t)((wn + jp * 16 + bRow) * 20 + ks * 8 + bKof)) * 4;
                uint32_t bh0, bh1, bh2, bh3;
                ldsm_x4(bh0, bh1, bh2, bh3, sBh + off);
#pragma unroll
                for (int i = 0; i < WM; i++) {
                    mma_f16(acc[i][2 * jp],     afh[i], bh0, bh1);
                    mma_f16(acc[i][2 * jp],     afl[i], bh0, bh1);
                    mma_f16(acc[i][2 * jp + 1], afh[i], bh2, bh3);
                    mma_f16(acc[i][2 * jp + 1], afl[i], bh2, bh3);
                }
            }
        }
        __syncthreads();
        buf ^= 1;
    }

    float* __restrict__ Cout = (mat == 0) ? C0 : (mat == 1) ? C1 : C2;
#pragma unroll
    for (int i = 0; i < WM; i++) {
        int r0 = bm + wm + i * 16 + g4;
#pragma unroll
        for (int j = 0; j < 8; j++) {
            int c = colbase + wn + j * 8 + 2 * t4;
            float2 v0 = {acc[i][j][0], acc[i][j][1]};
            float2 v1 = {acc[i][j][2], acc[i][j][3]};
            *(float2*)&Cout[(size_t)r0 * Nper + c]       = v0;
            *(float2*)&Cout[(size_t)(r0 + 8) * Nper + c] = v1;
        }
    }
}

// ---------------------------------------------------------------------------
// ef row mapping (N-side)
// ---------------------------------------------------------------------------
__device__ __forceinline__ const float* ef_row(const float* __restrict__ efbr,
                                               const float* __restrict__ we0,
                                               int g, int e) {
    if (e < 2 * CNUM)       return efbr + ((size_t)g * MPG + (e >> 1)) * CN;
    if (e < 2 * CNUM + NPG) return we0;
    return efbr + ((size_t)g * MPG + e - (CNUM + NPG)) * CN;
}

// ---------------------------------------------------------------------------
// Fused attention conv (R15 proven: precomputed packed CSR, small static smem)
// ---------------------------------------------------------------------------
template <int C, int H, int NODES, int EDGES, bool HAS_EF>
__global__ void __launch_bounds__(256) attn_conv(
    const float* __restrict__ q, const float* __restrict__ k,
    const float* __restrict__ v,
    const float* __restrict__ efbr, const float* __restrict__ we0,
    const int* __restrict__ gOff, const int* __restrict__ gAdj,
    float* __restrict__ outbuf, float* __restrict__ bnpart, float scale)
{
    constexpr int Oh = C / H;
    constexpr int WA = Oh / 8;
    constexpr int WB = C / 32;

    __shared__ int   sOff[NODES + 1];
    __shared__ int   sAdj[EDGES];
    __shared__ float sW[EDGES * H];
    __shared__ float sSumW[8 * H];
    __shared__ float sBN[2 * C];

    const int g = blockIdx.x, t = threadIdx.x;
    const int nb = g * NODES, eb = g * EDGES;
    const int warp = t >> 5, lane = t & 31;

    for (int i = t; i < NODES + 1; i += 256) sOff[i] = gOff[g * (NODES + 1) + i];
    for (int i = t; i < EDGES; i += 256) sAdj[i] = gAdj[eb + i];
    for (int i = t; i < 2 * C; i += 256) sBN[i] = 0.f;
    __syncthreads();

    const int h = lane >> 3, u = lane & 7;
    const int cA = h * Oh + u * WA;
    const int cB = lane * WB;
    const int headB = cB / Oh;

    float s1[WB], s2[WB];
#pragma unroll
    for (int j = 0; j < WB; j++) { s1[j] = 0.f; s2[j] = 0.f; }

    for (int d = warp; d < NODES; d += 8) {
        const int e0 = sOff[d], e1 = sOff[d + 1];

        float qv[WA];
        {
            const float* qr = q + (size_t)(nb + d) * C + cA;
            if constexpr (WA == 8) {
                float4 a = *(const float4*)qr, b = *(const float4*)(qr + 4);
                qv[0] = a.x; qv[1] = a.y; qv[2] = a.z; qv[3] = a.w;
                qv[4] = b.x; qv[5] = b.y; qv[6] = b.z; qv[7] = b.w;
            } else {
                float2 a = *(const float2*)qr;
                qv[0] = a.x; qv[1] = a.y;
            }
        }

        float mx = -INFINITY;
        for (int ii = e0; ii < e1; ii++) {
            int pk = sAdj[ii];
            int e = pk & 0xffff, s = pk >> 16;
            const float* kr = k + (size_t)(nb + s) * C + cA;
            float kk[WA];
            if constexpr (WA == 8) {
                float4 a = *(const float4*)kr, b = *(const float4*)(kr + 4);
                kk[0] = a.x; kk[1] = a.y; kk[2] = a.z; kk[3] = a.w;
                kk[4] = b.x; kk[5] = b.y; kk[6] = b.z; kk[7] = b.w;
            } else {
                float2 a = *(const float2*)kr;
                kk[0] = a.x; kk[1] = a.y;
            }
            if (HAS_EF) {
                const float* er = ef_row(efbr, we0, g, e) + cA;
                if constexpr (WA == 8) {
                    float4 a = *(const float4*)er, b = *(const float4*)(er + 4);
                    kk[0] += a.x; kk[1] += a.y; kk[2] += a.z; kk[3] += a.w;
                    kk[4] += b.x; kk[5] += b.y; kk[6] += b.z; kk[7] += b.w;
                } else {
                    float2 a = *(const float2*)er;
                    kk[0] += a.x; kk[1] += a.y;
                }
            }
            float p = 0.f;
#pragma unroll
            for (int j = 0; j < WA; j++) p += qv[j] * kk[j];
            p += __shfl_xor_sync(0xffffffffu, p, 1);
            p += __shfl_xor_sync(0xffffffffu, p, 2);
            p += __shfl_xor_sync(0xffffffffu, p, 4);
            float l = p * scale;
            l = (l > 0.f) ? l : 0.2f * l;
            if (u == 0) sW[e * H + h] = l;
            mx = fmaxf(mx, l);
        }
        __syncwarp();

        float sumh = 0.f;
        for (int ii = e0; ii < e1; ii++) {
            int e = sAdj[ii] & 0xffff;
            float w = expf(sW[e * H + h] - mx);
            if (u == 0) sW[e * H + h] = w;
            sumh += w;
        }
        if (u == 0) sSumW[warp * H + h] = sumh;
        __syncwarp();

        float acc[WB];
#pragma unroll
        for (int j = 0; j < WB; j++) acc[j] = 0.f;
        for (int ii = e0; ii < e1; ii++) {
            int pk = sAdj[ii];
            int e = pk & 0xffff, s = pk >> 16;
            const float w = sW[e * H + headB];
            const float* vr = v + (size_t)(nb + s) * C + cB;
            float vv[WB];
            if constexpr (WB == 8) {
                float4 a = *(const float4*)vr, b = *(const float4*)(vr + 4);
                vv[0] = a.x; vv[1] = a.y; vv[2] = a.z; vv[3] = a.w;
                vv[4] = b.x; vv[5] = b.y; vv[6] = b.z; vv[7] = b.w;
            } else {
                float2 a = *(const float2*)vr;
                vv[0] = a.x; vv[1] = a.y;
            }
            if (HAS_EF) {
                const float* er = ef_row(efbr, we0, g, e) + cB;
                if constexpr (WB == 8) {
                    float4 a = *(const float4*)er, b = *(const float4*)(er + 4);
                    vv[0] += a.x; vv[1] += a.y; vv[2] += a.z; vv[3] += a.w;
                    vv[4] += b.x; vv[5] += b.y; vv[6] += b.z; vv[7] += b.w;
                } else {
                    float2 a = *(const float2*)er;
                    vv[0] += a.x; vv[1] += a.y;
                }
            }
#pragma unroll
            for (int j = 0; j < WB; j++) acc[j] += w * vv[j];
        }

        const float denom = sSumW[warp * H + headB] + 1e-16f;
        float* orow = outbuf + (size_t)(nb + d) * C + cB;
        float o[WB];
#pragma unroll
        for (int j = 0; j < WB; j++) {
            o[j] = acc[j] / denom;
            s1[j] += o[j]; s2[j] += o[j] * o[j];
        }
        if constexpr (WB == 8) {
            *(float4*)orow       = make_float4(o[0], o[1], o[2], o[3]);
            *(float4*)(orow + 4) = make_float4(o[4], o[5], o[6], o[7]);
        } else {
            *(float2*)orow = make_float2(o[0], o[1]);
        }
    }

#pragma unroll
    for (int j = 0; j < WB; j++) {
        atomicAdd(&sBN[cB + j], s1[j]);
        atomicAdd(&sBN[C + cB + j], s2[j]);
    }
    __syncthreads();
    for (int i = t; i < 2 * C; i += 256)
        bnpart[(size_t)g * 2 * C + i] = sBN[i];
}

// ---------------------------------------------------------------------------
// BN stats reduce, parallel over channels (grid = C)
// ---------------------------------------------------------------------------
template <int C>
__global__ void bn_final3(const float* __restrict__ part,
                          float* __restrict__ mu, float* __restrict__ rstd,
                          int nblocks, int Nrows) {
    __shared__ float rs[256], rss[256];
    int c = blockIdx.x, t = threadIdx.x;
    float s = 0.f, ss = 0.f;
    for (int b = t; b < nblocks; b += 256) {
        s  += part[(size_t)b * 2 * C + c];
        ss += part[(size_t)b * 2 * C + C + c];
    }
    rs[t] = s; rss[t] = ss;
    __syncthreads();
    for (int o = 128; o > 0; o >>= 1) {
        if (t < o) { rs[t] += rs[t + o]; rss[t] += rss[t + o]; }
        __syncthreads();
    }
    if (t == 0) {
        float m = rs[0] / (float)Nrows;
        float v = rss[0] / (float)Nrows - m * m;
        mu[c] = m;
        rstd[c] = rsqrtf(v + 1e-5f);
    }
}

// ---------------------------------------------------------------------------
// BN apply variants (float4), with fused fp16 split outputs
// ---------------------------------------------------------------------------
template <int C, bool SUB>
__global__ void bn_apply4s(const float4* __restrict__ o, const float4* __restrict__ res,
                           const float* __restrict__ mu, const float* __restrict__ rstd,
                           const float* __restrict__ g, const float* __restrict__ b,
                           float4* __restrict__ out,
                           uint2* __restrict__ shi, uint2* __restrict__ slo, int n4) {
    int i = blockIdx.x * blockDim.x + threadIdx.x;
    if (i >= n4) return;
    int c = (i % (C / 4)) * 4;
    float4 ov = o[i], rv = res[i], y;
    y.x = fmaxf((ov.x - mu[c+0]) * rstd[c+0] * g[c+0] + b[c+0], 0.f);
    y.y = fmaxf((ov.y - mu[c+1]) * rstd[c+1] * g[c+1] + b[c+1], 0.f);
    y.z = fmaxf((ov.z - mu[c+2]) * rstd[c+2] * g[c+2] + b[c+2], 0.f);
    y.w = fmaxf((ov.w - mu[c+3]) * rstd[c+3] * g[c+3] + b[c+3], 0.f);
    float4 r;
    if (SUB) { r.x = rv.x - y.x; r.y = rv.y - y.y; r.z = rv.z - y.z; r.w = rv.w - y.w; }
    else     { r.x = rv.x + y.x; r.y = rv.y + y.y; r.z = rv.z + y.z; r.w = rv.w + y.w; }
    out[i] = r;
    uint2 hi, lo;
    split4(r, hi, lo);
    shi[i] = hi; slo[i] = lo;
}

__global__ void bn_apply_toedge4(const float4* __restrict__ o, const float4* __restrict__ res,
                                 const float* __restrict__ mu, const float* __restrict__ rstd,
                                 const float* __restrict__ gg, const float* __restrict__ bb,
                                 float4* __restrict__ brout, float4* __restrict__ ei,
                                 uint2* __restrict__ shi, uint2* __restrict__ slo) {
    int i = blockIdx.x * blockDim.x + threadIdx.x;
    if (i >= NE_NODES * (CE / 4)) return;
    int c4 = i & 15, c = c4 * 4;
    int row = i >> 4;
    int g = row >> 7, r = row & 127;
    float4 ov = o[i], rv = res[i], val;
    val.x = rv.x - fmaxf((ov.x - mu[c+0]) * rstd[c+0] * gg[c+0] + bb[c+0], 0.f);
    val.y = rv.y - fmaxf((ov.y - mu[c+1]) * rstd[c+1] * gg[c+1] + bb[c+1], 0.f);
    val.z = rv.z - fmaxf((ov.z - mu[c+2]) * rstd[c+2] * gg[c+2] + bb[c+2], 0.f);
    val.w = rv.w - fmaxf((ov.w - mu[c+3]) * rstd[c+3] * gg[c+3] + bb[c+3], 0.f);
    brout[i] = val;
    uint2 hi, lo;
    split4(val, hi, lo);
    shi[i] = hi; slo[i] = lo;
    size_t eib = (size_t)g * EPG;
    if (r < CNUM) {
        ei[(eib + 2 * r) * 16 + c4]     = val;
        ei[(eib + 2 * r + 1) * 16 + c4] = val;
    } else {
        ei[(eib + r + (CNUM + NPG)) * 16 + c4] = val;
    }
}

__global__ void bn_apply_sn4(const float4* __restrict__ o, const float4* __restrict__ res,
                             const float* __restrict__ mu, const float* __restrict__ rstd,
                             const float* __restrict__ gg, const float* __restrict__ bb,
                             float4* __restrict__ out, float4* __restrict__ sn) {
    int i = blockIdx.x * blockDim.x + threadIdx.x;
    if (i >= NN_NODES * (CN / 4)) return;
    int c4 = i & 63, c = c4 * 4;
    int row = i >> 6;
    float4 ov = o[i], rv = res[i], val;
    val.x = rv.x - fmaxf((ov.x - mu[c+0]) * rstd[c+0] * gg[c+0] + bb[c+0], 0.f);
    val.y = rv.y - fmaxf((ov.y - mu[c+1]) * rstd[c+1] * gg[c+1] + bb[c+1], 0.f);
    val.z = rv.z - fmaxf((ov.z - mu[c+2]) * rstd[c+2] * gg[c+2] + bb[c+2], 0.f);
    val.w = rv.w - fmaxf((ov.w - mu[c+3]) * rstd[c+3] * gg[c+3] + bb[c+3], 0.f);
    out[i] = val;
    if ((row & 63) == 63) sn[(size_t)(row >> 6) * 64 + c4] = val;
}

// vectorized: one float4 per thread
__global__ void onehot_fill4(float4* __restrict__ ei) {
    int i = blockIdx.x * blockDim.x + threadIdx.x;
    if (i >= BGR * NPG * (CE / 4)) return;
    int c4 = i & 15;
    int row = i >> 4;
    int g = row / NPG, rr = row % NPG;
    float4 v = (c4 == 0) ? make_float4(1.f, 0.f, 0.f, 0.f) : make_float4(0.f, 0.f, 0.f, 0.f);
    ei[((size_t)g * EPG + 2 * CNUM + rr) * 16 + c4] = v;
}

// ---------------------------------------------------------------------------
// Host orchestration (two streams, event fork/join)
// ---------------------------------------------------------------------------
static inline float* sym(const void* s) {
    void* p = nullptr;
    cudaGetSymbolAddress(&p, (const void*)s);
    return (float*)p;
}

static cudaStream_t make_stream() {
    cudaStream_t s;
    cudaStreamCreateWithFlags(&s, cudaStreamNonBlocking);
    return s;
}
static cudaEvent_t make_event() {
    cudaEvent_t e;
    cudaEventCreateWithFlags(&e, cudaEventDisableTiming);
    return e;
}

extern "C" void kernel_launch(void* const* d_in, const int* in_sizes, int n_in,
                              void* d_out, int out_size) {
    (void)in_sizes; (void)n_in; (void)out_size;
    const float* x    = (const float*)d_in[0];
    const int*   eiN  = (const int*)d_in[1];
    const float* brf  = (const float*)d_in[2];
    const int*   eiE  = (const int*)d_in[3];
    const float* WqE1 = (const float*)d_in[4];
    const float* WkE1 = (const float*)d_in[5];
    const float* WvE1 = (const float*)d_in[6];
    const float* gE1  = (const float*)d_in[7];
    const float* bE1  = (const float*)d_in[8];
    const float* Wq1  = (const float*)d_in[9];
    const float* Wk1  = (const float*)d_in[10];
    const float* Wv1  = (const float*)d_in[11];
    const float* We1  = (const float*)d_in[12];
    const float* gN1  = (const float*)d_in[13];
    const float* bN1  = (const float*)d_in[14];
    const float* WqE2 = (const float*)d_in[15];
    const float* WkE2 = (const float*)d_in[16];
    const float* WvE2 = (const float*)d_in[17];
    const float* gE2  = (const float*)d_in[18];
    const float* bE2  = (const float*)d_in[19];
    const float* Wq2  = (const float*)d_in[20];
    const float* Wk2  = (const float*)d_in[21];
    const float* Wv2  = (const float*)d_in[22];
    const float* We2  = (const float*)d_in[23];
    const float* gN2  = (const float*)d_in[24];
    const float* bN2  = (const float*)d_in[25];

    float* out = (float*)d_out;
    float* out2_buf = out + OFF_OUT2;
    float* ei2_buf  = out + OFF_EI;
    float* br2_buf  = out + OFF_BR;
    float* sn_buf   = out + OFF_SN;

    float* qE   = sym(g_qE);   float* kE   = sym(g_kE);   float* vE  = sym(g_vE);
    float* accE = sym(g_accE); float* br1  = sym(g_br1);
    float* efbr = sym(g_efbr); float* efbr2 = sym(g_efbr2);
    float* qN   = sym(g_qN);   float* kN   = sym(g_kN);   float* vN  = sym(g_vN);
    float* accN = sym(g_accN); float* out1 = sym(g_out1);
    float* bnpartE = sym(g_bnpartE); float* bnpartN = sym(g_bnpartN);
    float* muE = sym(g_muE); float* rstdE = sym(g_rstdE);
    float* muN = sym(g_muN); float* rstdN = sym(g_rstdN);
    uint32_t* ahiN = (uint32_t*)sym(g_ahiN); uint32_t* aloN = (uint32_t*)sym(g_aloN);
    uint32_t* ahiE = (uint32_t*)sym(g_ahiE); uint32_t* aloE = (uint32_t*)sym(g_aloE);
    uint32_t* ahiE2 = (uint32_t*)sym(g_ahiE2); uint32_t* aloE2 = (uint32_t*)sym(g_aloE2);
    uint32_t* whi = (uint32_t*)sym(g_wthi);
    int* offE = (int*)sym(g_offE); int* adjE = (int*)sym(g_adjE);
    int* offN = (int*)sym(g_offN); int* adjN = (int*)sym(g_adjN);

    const int* srcE = eiE;              const int* dstE = eiE + NE_EDGES;
    const int* srcN = eiN;              const int* dstN = eiN + NN_EDGES;

    const float scaleE = 0.25f;
    const float scaleN = 0.125f;

    const int nE2 = NE_NODES * CE / 2;
    const int nN2 = NN_NODES * CN / 2;
    const int nE4 = NE_NODES * CE / 4;
    const int nN4 = NN_NODES * CN / 4;

    const int SME = 2 * (2 * 256 + 64) * 20 * 4;    // 92160
    const int SMN = 2 * (2 * 128 + 128) * 20 * 4;   // 61440
    cudaFuncSetAttribute(hmma_gemm<2, 1>, cudaFuncAttributeMaxDynamicSharedMemorySize, SME);
    cudaFuncSetAttribute(hmma_gemm<2, 2>, cudaFuncAttributeMaxDynamicSharedMemorySize, SMN);

    static cudaStream_t s2 = make_stream();
    static cudaEvent_t evW   = make_event();
    static cudaEvent_t evQN1 = make_event();
    static cudaEvent_t evBr1 = make_event();
    static cudaEvent_t evEf2 = make_event();

    // ===== main: CSR + weights + constants + brf split =====
    csr_build<MPG, MPG * 4><<<BGR, 256>>>(srcE, dstE, offE, adjE);
    csr_build<NPG, EPG><<<BGR, 256>>>(srcN, dstN, offN, adjN);
    wsplit_all<<<(W_TOT + 255) / 256, 256>>>(WqE1, WkE1, WvE1, WqE2, WkE2, WvE2,
                                             We1, We2, Wq1, Wk1, Wv1, Wq2, Wk2, Wv2, whi);
    onehot_fill4<<<(BGR * NPG * (CE / 4)) / 256, 256>>>((float4*)ei2_buf);
    split_f16<<<(nE2 + 255) / 256, 256>>>((const float2*)brf, ahiE, aloE, nE2);
    cudaEventRecord(evW, 0);
    cudaStreamWaitEvent(s2, evW, 0);

    // ===== stream2: N1 prep =====
    split_f16<<<(nN2 + 255) / 256, 256, 0, s2>>>((const float2*)x, ahiN, aloN, nN2);
    hmma_gemm<2, 2><<<dim3(6, NN_NODES / 128), 256, SMN, s2>>>(
        ahiN, aloN, whi + W_N1, qN, kN, vN, NN_NODES, CN, 256, 2);
    cudaEventRecord(evQN1, s2);

    // ===== main: E1 chain =====
    hmma_gemm<2, 1><<<dim3(3, NE_NODES / 256), 256, SME>>>(
        ahiE, aloE, whi + W_E1, qE, kE, vE, NE_NODES, CE, 64, 1);
    attn_conv<CE, 4, MPG, MPG * 4, false><<<BGR, 256>>>(
        qE, kE, vE, nullptr, nullptr, offE, adjE, accE, bnpartE, scaleE);
    bn_final3<CE><<<CE, 256>>>(bnpartE, muE, rstdE, BGR, NE_NODES);
    bn_apply4s<CE, false><<<nE4 / 256, 256>>>(
        (const float4*)accE, (const float4*)brf, muE, rstdE, gE1, bE1,
        (float4*)br1, (uint2*)ahiE, (uint2*)aloE, nE4);
    cudaEventRecord(evBr1, 0);
    cudaStreamWaitEvent(s2, evBr1, 0);

    // ===== main: ef1 + N1 attn chain =====
    hmma_gemm<2, 2><<<dim3(2, NE_NODES / 128), 256, SMN>>>(
        ahiE, aloE, whi + W_WE1, efbr, efbr, efbr, NE_NODES, CE, 256, 2);
    cudaStreamWaitEvent(0, evQN1, 0);
    attn_conv<CN, 4, NPG, EPG, true><<<BGR, 256>>>(
        qN, kN, vN, efbr, We1, offN, adjN, accN, bnpartN, scaleN);
    bn_final3<CN><<<CN, 256>>>(bnpartN, muN, rstdN, BGR, NN_NODES);
    bn_apply4s<CN, false><<<nN4 / 256, 256>>>(
        (const float4*)accN, (const float4*)x, muN, rstdN, gN1, bN1,
        (float4*)out1, (uint2*)ahiN, (uint2*)aloN, nN4);

    // ===== stream2: E2 chain =====
    hmma_gemm<2, 1><<<dim3(3, NE_NODES / 256), 256, SME, s2>>>(
        ahiE, aloE, whi + W_E2, qE, kE, vE, NE_NODES, CE, 64, 1);
    attn_conv<CE, 4, MPG, MPG * 4, false><<<BGR, 256, 0, s2>>>(
        qE, kE, vE, nullptr, nullptr, offE, adjE, accE, bnpartE, scaleE);
    bn_final3<CE><<<CE, 256, 0, s2>>>(bnpartE, muE, rstdE, BGR, NE_NODES);
    bn_apply_toedge4<<<nE4 / 256, 256, 0, s2>>>(
        (const float4*)accE, (const float4*)br1, muE, rstdE, gE2, bE2,
        (float4*)br2_buf, (float4*)ei2_buf, (uint2*)ahiE2, (uint2*)aloE2);
    hmma_gemm<2, 2><<<dim3(2, NE_NODES / 128), 256, SMN, s2>>>(
        ahiE2, aloE2, whi + W_WE2, efbr2, efbr2, efbr2, NE_NODES, CE, 256, 2);
    cudaEventRecord(evEf2, s2);

    // ===== main: N2 chain =====
    hmma_gemm<2, 2><<<dim3(6, NN_NODES / 128), 256, SMN>>>(
        ahiN, aloN, whi + W_N2, qN, kN, vN, NN_NODES, CN, 256, 2);
    cudaStreamWaitEvent(0, evEf2, 0);
    attn_conv<CN, 4, NPG, EPG, true><<<BGR, 256>>>(
        qN, kN, vN, efbr2, We2, offN, adjN, accN, bnpartN, scaleN);
    bn_final3<CN><<<CN, 256>>>(bnpartN, muN, rstdN, BGR, NN_NODES);
    bn_apply_sn4<<<nN4 / 256, 256>>>(
        (const float4*)accN, (const float4*)out1, muN, rstdN, gN2, bN2,
        (float4*)out2_buf, (float4*)sn_buf);
}

// round 17
// speedup vs baseline: 1.5281x; 1.1591x over previous
#include <cuda_runtime.h>
#include <cuda_fp16.h>
#include <cstdint>
#include <cstring>
#include <math.h>

// ---------------------------------------------------------------------------
// Problem constants
// ---------------------------------------------------------------------------
#define BGR   512
#define NPG   64
#define CNUM  8
#define MPG   128
#define CN    256
#define CE    64
#define EPG   200

#define NE_NODES (BGR*MPG)        // 65536
#define NE_EDGES (BGR*MPG*4)      // 262144
#define NN_NODES (BGR*NPG)        // 32768
#define NN_EDGES (BGR*EPG)        // 102400

#define OFF_OUT2 0
#define OFF_EI   ((size_t)NN_NODES*CN)
#define OFF_BR   (OFF_EI + (size_t)NN_EDGES*CE)
#define OFF_SN   (OFF_BR + (size_t)NE_NODES*CE)

// weight segment offsets (u32 pair units)
#define W_E1  0
#define W_E2  6144
#define W_WE1 12288
#define W_WE2 20480
#define W_N1  28672
#define W_N2  126976
#define W_TOT 225280

// ---------------------------------------------------------------------------
// Scratch (device globals)
// ---------------------------------------------------------------------------
__device__ float g_qE[(size_t)NE_NODES*CE];
__device__ float g_kE[(size_t)NE_NODES*CE];
__device__ float g_vE[(size_t)NE_NODES*CE];
__device__ float g_accE[(size_t)NE_NODES*CE];
__device__ float g_br1[(size_t)NE_NODES*CE];

__device__ float g_efbr[(size_t)NE_NODES*CN];
__device__ float g_efbr2[(size_t)NE_NODES*CN];
__device__ float g_qN[(size_t)NN_NODES*CN];
__device__ float g_kN[(size_t)NN_NODES*CN];
__device__ float g_vN[(size_t)NN_NODES*CN];
__device__ float g_accN[(size_t)NN_NODES*CN];
__device__ float g_out1[(size_t)NN_NODES*CN];

__device__ float g_bnpartE[(size_t)BGR * 2 * CE];
__device__ float g_bnpartN[(size_t)BGR * 2 * CN];
__device__ float g_muE[CE];
__device__ float g_rstdE[CE];
__device__ float g_muN[CN];
__device__ float g_rstdN[CN];

__device__ uint32_t g_ahiN[(size_t)NN_NODES*CN/2];
__device__ uint32_t g_ahiE[(size_t)NE_NODES*CE/2];
__device__ uint32_t g_ahiE2[(size_t)NE_NODES*CE/2];
__device__ uint32_t g_wthi[W_TOT];

// precomputed CSR (packed adj: (src_local<<16)|edge_local)
__device__ int g_offE[(size_t)BGR * (MPG + 1)];
__device__ int g_adjE[(size_t)NE_EDGES];
__device__ int g_offN[(size_t)BGR * (NPG + 1)];
__device__ int g_adjN[(size_t)NN_EDGES];

// ---------------------------------------------------------------------------
// fp16 conversion helpers (single-pass: both operands rounded to fp16)
// ---------------------------------------------------------------------------
__device__ __forceinline__ uint32_t pack_f16(float x, float y) {
    __half hx = __float2half_rn(x), hy = __float2half_rn(y);
    return (uint32_t)__half_as_ushort(hx) | ((uint32_t)__half_as_ushort(hy) << 16);
}
__device__ __forceinline__ uint2 cvt4(float4 v) {
    uint2 r;
    r.x = pack_f16(v.x, v.y);
    r.y = pack_f16(v.z, v.w);
    return r;
}

__global__ void cvt_f16(const float2* __restrict__ a, uint32_t* __restrict__ hi, int n2) {
    int i = blockIdx.x * blockDim.x + threadIdx.x;
    if (i >= n2) return;
    float2 v = a[i];
    hi[i] = pack_f16(v.x, v.y);
}

// All 8 weight matrices -> fp16, segmented layout.
__global__ void wsplit_all(
    const float* __restrict__ WqE1, const float* __restrict__ WkE1, const float* __restrict__ WvE1,
    const float* __restrict__ WqE2, const float* __restrict__ WkE2, const float* __restrict__ WvE2,
    const float* __restrict__ We1,  const float* __restrict__ We2,
    const float* __restrict__ Wq1,  const float* __restrict__ Wk1,  const float* __restrict__ Wv1,
    const float* __restrict__ Wq2,  const float* __restrict__ Wk2,  const float* __restrict__ Wv2,
    uint32_t* __restrict__ hi)
{
    int i = blockIdx.x * blockDim.x + threadIdx.x;
    if (i >= W_TOT) return;
    const float* W; int Nper, n, kp;
    if (i < W_WE1) {
        int l = i / 6144, r = i % 6144;
        int mat = r / 2048, rr = r % 2048;
        n = rr / 32; kp = rr % 32; Nper = 64;
        const float* tab[6] = {WqE1, WkE1, WvE1, WqE2, WkE2, WvE2};
        W = tab[l * 3 + mat];
    } else if (i < W_N1) {
        int r = i - W_WE1;
        int l = r / 8192; r %= 8192;
        n = r / 32; kp = r % 32; Nper = 256;
        W = l ? We2 : We1;
    } else {
        int r = i - W_N1;
        int l = r / 98304; r %= 98304;
        int mat = r / 32768, rr = r % 32768;
        n = rr / 128; kp = rr % 128; Nper = 256;
        const float* tab[6] = {Wq1, Wk1, Wv1, Wq2, Wk2, Wv2};
        W = tab[l * 3 + mat];
    }
    float vx = W[(size_t)(2 * kp) * Nper + n];
    float vy = W[(size_t)(2 * kp + 1) * Nper + n];
    hi[i] = pack_f16(vx, vy);
}

// ---------------------------------------------------------------------------
// CSR build (once per side): block per graph, packed adj
// ---------------------------------------------------------------------------
template <int NODES, int EDGES>
__global__ void csr_build(const int* __restrict__ src, const int* __restrict__ dst,
                          int* __restrict__ gOff, int* __restrict__ gAdj) {
    __shared__ int sOff[NODES + 1];
    __shared__ int sCur[NODES];
    const int g = blockIdx.x, t = threadIdx.x;
    const int nb = g * NODES, eb = g * EDGES;
    for (int i = t; i < NODES; i += 256) sCur[i] = 0;
    __syncthreads();
    for (int e = t; e < EDGES; e += 256) atomicAdd(&sCur[dst[eb + e] - nb], 1);
    __syncthreads();
    if (t == 0) {
        int run = 0;
        for (int i = 0; i < NODES; i++) { sOff[i] = run; run += sCur[i]; }
        sOff[NODES] = run;
    }
    __syncthreads();
    for (int i = t; i < NODES; i += 256) sCur[i] = sOff[i];
    __syncthreads();
    for (int e = t; e < EDGES; e += 256) {
        int d = dst[eb + e] - nb;
        int pos = atomicAdd(&sCur[d], 1);
        gAdj[eb + pos] = ((src[eb + e] - nb) << 16) | e;
    }
    for (int i = t; i < NODES + 1; i += 256) gOff[g * (NODES + 1) + i] = sOff[i];
}

// ---------------------------------------------------------------------------
// mma.sync (f16) + ldmatrix + cp.async
// ---------------------------------------------------------------------------
__device__ __forceinline__ void mma_f16(float* c, const uint32_t* a,
                                        uint32_t b0, uint32_t b1) {
    asm volatile(
        "mma.sync.aligned.m16n8k16.row.col.f32.f16.f16.f32 "
        "{%0,%1,%2,%3}, {%4,%5,%6,%7}, {%8,%9}, {%0,%1,%2,%3};"
        : "+f"(c[0]), "+f"(c[1]), "+f"(c[2]), "+f"(c[3])
        : "r"(a[0]), "r"(a[1]), "r"(a[2]), "r"(a[3]), "r"(b0), "r"(b1));
}

__device__ __forceinline__ void ldsm_x4(uint32_t& r0, uint32_t& r1,
                                        uint32_t& r2, uint32_t& r3, uint32_t addr) {
    asm volatile("ldmatrix.sync.aligned.m8n8.x4.shared.b16 {%0,%1,%2,%3}, [%4];"
                 : "=r"(r0), "=r"(r1), "=r"(r2), "=r"(r3) : "r"(addr));
}

__device__ __forceinline__ uint32_t smem_u32(const void* p) {
    uint32_t a;
    asm("{ .reg .u64 t; cvta.to.shared.u64 t, %1; cvt.u32.u64 %0, t; }" : "=r"(a) : "l"(p));
    return a;
}

__device__ __forceinline__ void cp_async16(uint32_t saddr, const void* g) {
    asm volatile("cp.async.cg.shared.global [%0], [%1], 16;" :: "r"(saddr), "l"(g));
}
__device__ __forceinline__ void cp_commit() {
    asm volatile("cp.async.commit_group;" ::: "memory");
}
template<int N>
__device__ __forceinline__ void cp_wait() {
    asm volatile("cp.async.wait_group %0;" :: "n"(N) : "memory");
}

// ---------------------------------------------------------------------------
// HMMA fp16 GEMM, single-pass fp16(A) x fp16(W), cp.async double-buffered.
// ---------------------------------------------------------------------------
template<int WM, int NWN>
__global__ void __launch_bounds__(256) hmma_gemm(
    const uint32_t* __restrict__ ahi, const uint32_t* __restrict__ bhi,
    float* __restrict__ C0, float* __restrict__ C1, float* __restrict__ C2,
    int M, int K, int Nper, int matdiv)
{
    constexpr int BN  = NWN * 64;
    constexpr int NWM = 8 / NWN;
    constexpr int BM  = NWM * WM * 16;
    constexpr int BUFSZ = (BM + BN) * 20;
    const int K2 = K >> 1;

    extern __shared__ uint32_t sm[];
    const uint32_t smb = smem_u32(sm);

    const int t = threadIdx.x, warp = t >> 5, lane = t & 31;
    const int mat     = blockIdx.x / matdiv;
    const int colbase = (blockIdx.x % matdiv) * BN;
    const int bm = blockIdx.y * BM;
    const int wm = (warp % NWM) * WM * 16;
    const int wn = (warp / NWM) * 64;
    const int g4 = lane >> 2, t4 = lane & 3;

    const int aRow = (lane & 7) + ((lane >> 3) & 1) * 8;
    const int aKof = (lane >> 4) * 4;
    const int bRow = (lane & 7) + (lane >> 4) * 8;
    const int bKof = ((lane >> 3) & 1) * 4;

    const int brow_base = mat * Nper + colbase;

    auto stage = [&](int kc, int buf) {
        uint32_t base = smb + (uint32_t)buf * BUFSZ * 4;
        for (int idx = t; idx < BM * 4; idx += 256) {
            int r = idx >> 2, q = idx & 3;
            size_t gi = (size_t)(bm + r) * K2 + kc * 16 + q * 4;
            uint32_t so = (uint32_t)(r * 20 + q * 4) * 4;
            cp_async16(base + so, ahi + gi);
        }
        for (int idx = t; idx < BN * 4; idx += 256) {
            int r = idx >> 2, q = idx & 3;
            size_t gi = (size_t)(brow_base + r) * K2 + kc * 16 + q * 4;
            uint32_t so = (uint32_t)(r * 20 + q * 4) * 4;
            cp_async16(base + (uint32_t)(BM * 20) * 4 + so, bhi + gi);
        }
    };

    float acc[WM][8][4];
#pragma unroll
    for (int i = 0; i < WM; i++)
#pragma unroll
        for (int j = 0; j < 8; j++)
#pragma unroll
            for (int q = 0; q < 4; q++) acc[i][j][q] = 0.f;

    const int nch = K2 / 16;
    stage(0, 0);
    cp_commit();

    int buf = 0;
    for (int kc = 0; kc < nch; kc++) {
        if (kc + 1 < nch) {
            stage(kc + 1, buf ^ 1);
            cp_commit();
            cp_wait<1>();
        } else {
            cp_wait<0>();
        }
        __syncthreads();

        uint32_t base = smb + (uint32_t)buf * BUFSZ * 4;
        const uint32_t sAh = base;
        const uint32_t sBh = base + (uint32_t)(BM * 20) * 4;

#pragma unroll
        for (int ks = 0; ks < 2; ks++) {
            uint32_t afh[WM][4];
#pragma unroll
            for (int i = 0; i < WM; i++) {
                uint32_t off = ((uint32_t)((wm + i * 16 + aRow) * 20 + ks * 8 + aKof)) * 4;
                ldsm_x4(afh[i][0], afh[i][1], afh[i][2], afh[i][3], sAh + off);
            }
#pragma unroll
            for (int jp = 0; jp < 4; jp++) {
                uint32_t off = ((uint32_t)((wn + jp * 16 + bRow) * 20 + ks * 8 + bKof)) * 4;
                uint32_t bh0, bh1, bh2, bh3;
                ldsm_x4(bh0, bh1, bh2, bh3, sBh + off);
#pragma unroll
                for (int i = 0; i < WM; i++) {
                    mma_f16(acc[i][2 * jp],     afh[i], bh0, bh1);
                    mma_f16(acc[i][2 * jp + 1], afh[i], bh2, bh3);
                }
            }
        }
        __syncthreads();
        buf ^= 1;
    }

    float* __restrict__ Cout = (mat == 0) ? C0 : (mat == 1) ? C1 : C2;
#pragma unroll
    for (int i = 0; i < WM; i++) {
        int r0 = bm + wm + i * 16 + g4;
#pragma unroll
        for (int j = 0; j < 8; j++) {
            int c = colbase + wn + j * 8 + 2 * t4;
            float2 v0 = {acc[i][j][0], acc[i][j][1]};
            float2 v1 = {acc[i][j][2], acc[i][j][3]};
            *(float2*)&Cout[(size_t)r0 * Nper + c]       = v0;
            *(float2*)&Cout[(size_t)(r0 + 8) * Nper + c] = v1;
        }
    }
}

// ---------------------------------------------------------------------------
// ef row mapping (N-side)
// ---------------------------------------------------------------------------
__device__ __forceinline__ const float* ef_row(const float* __restrict__ efbr,
                                               const float* __restrict__ we0,
                                               int g, int e) {
    if (e < 2 * CNUM)       return efbr + ((size_t)g * MPG + (e >> 1)) * CN;
    if (e < 2 * CNUM + NPG) return we0;
    return efbr + ((size_t)g * MPG + e - (CNUM + NPG)) * CN;
}

// ---------------------------------------------------------------------------
// Fused attention conv (R15 proven: precomputed packed CSR, small static smem)
// ---------------------------------------------------------------------------
template <int C, int H, int NODES, int EDGES, bool HAS_EF>
__global__ void __launch_bounds__(256) attn_conv(
    const float* __restrict__ q, const float* __restrict__ k,
    const float* __restrict__ v,
    const float* __restrict__ efbr, const float* __restrict__ we0,
    const int* __restrict__ gOff, const int* __restrict__ gAdj,
    float* __restrict__ outbuf, float* __restrict__ bnpart, float scale)
{
    constexpr int Oh = C / H;
    constexpr int WA = Oh / 8;
    constexpr int WB = C / 32;

    __shared__ int   sOff[NODES + 1];
    __shared__ int   sAdj[EDGES];
    __shared__ float sW[EDGES * H];
    __shared__ float sSumW[8 * H];
    __shared__ float sBN[2 * C];

    const int g = blockIdx.x, t = threadIdx.x;
    const int nb = g * NODES, eb = g * EDGES;
    const int warp = t >> 5, lane = t & 31;

    for (int i = t; i < NODES + 1; i += 256) sOff[i] = gOff[g * (NODES + 1) + i];
    for (int i = t; i < EDGES; i += 256) sAdj[i] = gAdj[eb + i];
    for (int i = t; i < 2 * C; i += 256) sBN[i] = 0.f;
    __syncthreads();

    const int h = lane >> 3, u = lane & 7;
    const int cA = h * Oh + u * WA;
    const int cB = lane * WB;
    const int headB = cB / Oh;

    float s1[WB], s2[WB];
#pragma unroll
    for (int j = 0; j < WB; j++) { s1[j] = 0.f; s2[j] = 0.f; }

    for (int d = warp; d < NODES; d += 8) {
        const int e0 = sOff[d], e1 = sOff[d + 1];

        float qv[WA];
        {
            const float* qr = q + (size_t)(nb + d) * C + cA;
            if constexpr (WA == 8) {
                float4 a = *(const float4*)qr, b = *(const float4*)(qr + 4);
                qv[0] = a.x; qv[1] = a.y; qv[2] = a.z; qv[3] = a.w;
                qv[4] = b.x; qv[5] = b.y; qv[6] = b.z; qv[7] = b.w;
            } else {
                float2 a = *(const float2*)qr;
                qv[0] = a.x; qv[1] = a.y;
            }
        }

        float mx = -INFINITY;
        for (int ii = e0; ii < e1; ii++) {
            int pk = sAdj[ii];
            int e = pk & 0xffff, s = pk >> 16;
            const float* kr = k + (size_t)(nb + s) * C + cA;
            float kk[WA];
            if constexpr (WA == 8) {
                float4 a = *(const float4*)kr, b = *(const float4*)(kr + 4);
                kk[0] = a.x; kk[1] = a.y; kk[2] = a.z; kk[3] = a.w;
                kk[4] = b.x; kk[5] = b.y; kk[6] = b.z; kk[7] = b.w;
            } else {
                float2 a = *(const float2*)kr;
                kk[0] = a.x; kk[1] = a.y;
            }
            if (HAS_EF) {
                const float* er = ef_row(efbr, we0, g, e) + cA;
                if constexpr (WA == 8) {
                    float4 a = *(const float4*)er, b = *(const float4*)(er + 4);
                    kk[0] += a.x; kk[1] += a.y; kk[2] += a.z; kk[3] += a.w;
                    kk[4] += b.x; kk[5] += b.y; kk[6] += b.z; kk[7] += b.w;
                } else {
                    float2 a = *(const float2*)er;
                    kk[0] += a.x; kk[1] += a.y;
                }
            }
            float p = 0.f;
#pragma unroll
            for (int j = 0; j < WA; j++) p += qv[j] * kk[j];
            p += __shfl_xor_sync(0xffffffffu, p, 1);
            p += __shfl_xor_sync(0xffffffffu, p, 2);
            p += __shfl_xor_sync(0xffffffffu, p, 4);
            float l = p * scale;
            l = (l > 0.f) ? l : 0.2f * l;
            if (u == 0) sW[e * H + h] = l;
            mx = fmaxf(mx, l);
        }
        __syncwarp();

        float sumh = 0.f;
        for (int ii = e0; ii < e1; ii++) {
            int e = sAdj[ii] & 0xffff;
            float w = expf(sW[e * H + h] - mx);
            if (u == 0) sW[e * H + h] = w;
            sumh += w;
        }
        if (u == 0) sSumW[warp * H + h] = sumh;
        __syncwarp();

        float acc[WB];
#pragma unroll
        for (int j = 0; j < WB; j++) acc[j] = 0.f;
        for (int ii = e0; ii < e1; ii++) {
            int pk = sAdj[ii];
            int e = pk & 0xffff, s = pk >> 16;
            const float w = sW[e * H + headB];
            const float* vr = v + (size_t)(nb + s) * C + cB;
            float vv[WB];
            if constexpr (WB == 8) {
                float4 a = *(const float4*)vr, b = *(const float4*)(vr + 4);
                vv[0] = a.x; vv[1] = a.y; vv[2] = a.z; vv[3] = a.w;
                vv[4] = b.x; vv[5] = b.y; vv[6] = b.z; vv[7] = b.w;
            } else {
                float2 a = *(const float2*)vr;
                vv[0] = a.x; vv[1] = a.y;
            }
            if (HAS_EF) {
                const float* er = ef_row(efbr, we0, g, e) + cB;
                if constexpr (WB == 8) {
                    float4 a = *(const float4*)er, b = *(const float4*)(er + 4);
                    vv[0] += a.x; vv[1] += a.y; vv[2] += a.z; vv[3] += a.w;
                    vv[4] += b.x; vv[5] += b.y; vv[6] += b.z; vv[7] += b.w;
                } else {
                    float2 a = *(const float2*)er;
                    vv[0] += a.x; vv[1] += a.y;
                }
            }
#pragma unroll
            for (int j = 0; j < WB; j++) acc[j] += w * vv[j];
        }

        const float denom = sSumW[warp * H + headB] + 1e-16f;
        float* orow = outbuf + (size_t)(nb + d) * C + cB;
        float o[WB];
#pragma unroll
        for (int j = 0; j < WB; j++) {
            o[j] = acc[j] / denom;
            s1[j] += o[j]; s2[j] += o[j] * o[j];
        }
        if constexpr (WB == 8) {
            *(float4*)orow       = make_float4(o[0], o[1], o[2], o[3]);
            *(float4*)(orow + 4) = make_float4(o[4], o[5], o[6], o[7]);
        } else {
            *(float2*)orow = make_float2(o[0], o[1]);
        }
    }

#pragma unroll
    for (int j = 0; j < WB; j++) {
        atomicAdd(&sBN[cB + j], s1[j]);
        atomicAdd(&sBN[C + cB + j], s2[j]);
    }
    __syncthreads();
    for (int i = t; i < 2 * C; i += 256)
        bnpart[(size_t)g * 2 * C + i] = sBN[i];
}

// ---------------------------------------------------------------------------
// BN stats reduce, parallel over channels (grid = C)
// ---------------------------------------------------------------------------
template <int C>
__global__ void bn_final3(const float* __restrict__ part,
                          float* __restrict__ mu, float* __restrict__ rstd,
                          int nblocks, int Nrows) {
    __shared__ float rs[256], rss[256];
    int c = blockIdx.x, t = threadIdx.x;
    float s = 0.f, ss = 0.f;
    for (int b = t; b < nblocks; b += 256) {
        s  += part[(size_t)b * 2 * C + c];
        ss += part[(size_t)b * 2 * C + C + c];
    }
    rs[t] = s; rss[t] = ss;
    __syncthreads();
    for (int o = 128; o > 0; o >>= 1) {
        if (t < o) { rs[t] += rs[t + o]; rss[t] += rss[t + o]; }
        __syncthreads();
    }
    if (t == 0) {
        float m = rs[0] / (float)Nrows;
        float v = rss[0] / (float)Nrows - m * m;
        mu[c] = m;
        rstd[c] = rsqrtf(v + 1e-5f);
    }
}

// ---------------------------------------------------------------------------
// BN apply variants (float4), with fused fp16 conversion outputs
// ---------------------------------------------------------------------------
template <int C, bool SUB>
__global__ void bn_apply4s(const float4* __restrict__ o, const float4* __restrict__ res,
                           const float* __restrict__ mu, const float* __restrict__ rstd,
                           const float* __restrict__ g, const float* __restrict__ b,
                           float4* __restrict__ out,
                           uint2* __restrict__ shi, int n4) {
    int i = blockIdx.x * blockDim.x + threadIdx.x;
    if (i >= n4) return;
    int c = (i % (C / 4)) * 4;
    float4 ov = o[i], rv = res[i], y;
    y.x = fmaxf((ov.x - mu[c+0]) * rstd[c+0] * g[c+0] + b[c+0], 0.f);
    y.y = fmaxf((ov.y - mu[c+1]) * rstd[c+1] * g[c+1] + b[c+1], 0.f);
    y.z = fmaxf((ov.z - mu[c+2]) * rstd[c+2] * g[c+2] + b[c+2], 0.f);
    y.w = fmaxf((ov.w - mu[c+3]) * rstd[c+3] * g[c+3] + b[c+3], 0.f);
    float4 r;
    if (SUB) { r.x = rv.x - y.x; r.y = rv.y - y.y; r.z = rv.z - y.z; r.w = rv.w - y.w; }
    else     { r.x = rv.x + y.x; r.y = rv.y + y.y; r.z = rv.z + y.z; r.w = rv.w + y.w; }
    out[i] = r;
    shi[i] = cvt4(r);
}

__global__ void bn_apply_toedge4(const float4* __restrict__ o, const float4* __restrict__ res,
                                 const float* __restrict__ mu, const float* __restrict__ rstd,
                                 const float* __restrict__ gg, const float* __restrict__ bb,
                                 float4* __restrict__ brout, float4* __restrict__ ei,
                                 uint2* __restrict__ shi) {
    int i = blockIdx.x * blockDim.x + threadIdx.x;
    if (i >= NE_NODES * (CE / 4)) return;
    int c4 = i & 15, c = c4 * 4;
    int row = i >> 4;
    int g = row >> 7, r = row & 127;
    float4 ov = o[i], rv = res[i], val;
    val.x = rv.x - fmaxf((ov.x - mu[c+0]) * rstd[c+0] * gg[c+0] + bb[c+0], 0.f);
    val.y = rv.y - fmaxf((ov.y - mu[c+1]) * rstd[c+1] * gg[c+1] + bb[c+1], 0.f);
    val.z = rv.z - fmaxf((ov.z - mu[c+2]) * rstd[c+2] * gg[c+2] + bb[c+2], 0.f);
    val.w = rv.w - fmaxf((ov.w - mu[c+3]) * rstd[c+3] * gg[c+3] + bb[c+3], 0.f);
    brout[i] = val;
    shi[i] = cvt4(val);
    size_t eib = (size_t)g * EPG;
    if (r < CNUM) {
        ei[(eib + 2 * r) * 16 + c4]     = val;
        ei[(eib + 2 * r + 1) * 16 + c4] = val;
    } else {
        ei[(eib + r + (CNUM + NPG)) * 16 + c4] = val;
    }
}

__global__ void bn_apply_sn4(const float4* __restrict__ o, const float4* __restrict__ res,
                             const float* __restrict__ mu, const float* __restrict__ rstd,
                             const float* __restrict__ gg, const float* __restrict__ bb,
                             float4* __restrict__ out, float4* __restrict__ sn) {
    int i = blockIdx.x * blockDim.x + threadIdx.x;
    if (i >= NN_NODES * (CN / 4)) return;
    int c4 = i & 63, c = c4 * 4;
    int row = i >> 6;
    float4 ov = o[i], rv = res[i], val;
    val.x = rv.x - fmaxf((ov.x - mu[c+0]) * rstd[c+0] * gg[c+0] + bb[c+0], 0.f);
    val.y = rv.y - fmaxf((ov.y - mu[c+1]) * rstd[c+1] * gg[c+1] + bb[c+1], 0.f);
    val.z = rv.z - fmaxf((ov.z - mu[c+2]) * rstd[c+2] * gg[c+2] + bb[c+2], 0.f);
    val.w = rv.w - fmaxf((ov.w - mu[c+3]) * rstd[c+3] * gg[c+3] + bb[c+3], 0.f);
    out[i] = val;
    if ((row & 63) == 63) sn[(size_t)(row >> 6) * 64 + c4] = val;
}

__global__ void onehot_fill4(float4* __restrict__ ei) {
    int i = blockIdx.x * blockDim.x + threadIdx.x;
    if (i >= BGR * NPG * (CE / 4)) return;
    int c4 = i & 15;
    int row = i >> 4;
    int g = row / NPG, rr = row % NPG;
    float4 v = (c4 == 0) ? make_float4(1.f, 0.f, 0.f, 0.f) : make_float4(0.f, 0.f, 0.f, 0.f);
    ei[((size_t)g * EPG + 2 * CNUM + rr) * 16 + c4] = v;
}

// ---------------------------------------------------------------------------
// Host orchestration (two streams, event fork/join)
// ---------------------------------------------------------------------------
static inline float* sym(const void* s) {
    void* p = nullptr;
    cudaGetSymbolAddress(&p, (const void*)s);
    return (float*)p;
}

static cudaStream_t make_stream() {
    cudaStream_t s;
    cudaStreamCreateWithFlags(&s, cudaStreamNonBlocking);
    return s;
}
static cudaEvent_t make_event() {
    cudaEvent_t e;
    cudaEventCreateWithFlags(&e, cudaEventDisableTiming);
    return e;
}

extern "C" void kernel_launch(void* const* d_in, const int* in_sizes, int n_in,
                              void* d_out, int out_size) {
    (void)in_sizes; (void)n_in; (void)out_size;
    const float* x    = (const float*)d_in[0];
    const int*   eiN  = (const int*)d_in[1];
    const float* brf  = (const float*)d_in[2];
    const int*   eiE  = (const int*)d_in[3];
    const float* WqE1 = (const float*)d_in[4];
    const float* WkE1 = (const float*)d_in[5];
    const float* WvE1 = (const float*)d_in[6];
    const float* gE1  = (const float*)d_in[7];
    const float* bE1  = (const float*)d_in[8];
    const float* Wq1  = (const float*)d_in[9];
    const float* Wk1  = (const float*)d_in[10];
    const float* Wv1  = (const float*)d_in[11];
    const float* We1  = (const float*)d_in[12];
    const float* gN1  = (const float*)d_in[13];
    const float* bN1  = (const float*)d_in[14];
    const float* WqE2 = (const float*)d_in[15];
    const float* WkE2 = (const float*)d_in[16];
    const float* WvE2 = (const float*)d_in[17];
    const float* gE2  = (const float*)d_in[18];
    const float* bE2  = (const float*)d_in[19];
    const float* Wq2  = (const float*)d_in[20];
    const float* Wk2  = (const float*)d_in[21];
    const float* Wv2  = (const float*)d_in[22];
    const float* We2  = (const float*)d_in[23];
    const float* gN2  = (const float*)d_in[24];
    const float* bN2  = (const float*)d_in[25];

    float* out = (float*)d_out;
    float* out2_buf = out + OFF_OUT2;
    float* ei2_buf  = out + OFF_EI;
    float* br2_buf  = out + OFF_BR;
    float* sn_buf   = out + OFF_SN;

    float* qE   = sym(g_qE);   float* kE   = sym(g_kE);   float* vE  = sym(g_vE);
    float* accE = sym(g_accE); float* br1  = sym(g_br1);
    float* efbr = sym(g_efbr); float* efbr2 = sym(g_efbr2);
    float* qN   = sym(g_qN);   float* kN   = sym(g_kN);   float* vN  = sym(g_vN);
    float* accN = sym(g_accN); float* out1 = sym(g_out1);
    float* bnpartE = sym(g_bnpartE); float* bnpartN = sym(g_bnpartN);
    float* muE = sym(g_muE); float* rstdE = sym(g_rstdE);
    float* muN = sym(g_muN); float* rstdN = sym(g_rstdN);
    uint32_t* ahiN = (uint32_t*)sym(g_ahiN);
    uint32_t* ahiE = (uint32_t*)sym(g_ahiE);
    uint32_t* ahiE2 = (uint32_t*)sym(g_ahiE2);
    uint32_t* whi = (uint32_t*)sym(g_wthi);
    int* offE = (int*)sym(g_offE); int* adjE = (int*)sym(g_adjE);
    int* offN = (int*)sym(g_offN); int* adjN = (int*)sym(g_adjN);

    const int* srcE = eiE;              const int* dstE = eiE + NE_EDGES;
    const int* srcN = eiN;              const int* dstN = eiN + NN_EDGES;

    const float scaleE = 0.25f;
    const float scaleN = 0.125f;

    const int nE2 = NE_NODES * CE / 2;
    const int nN2 = NN_NODES * CN / 2;
    const int nE4 = NE_NODES * CE / 4;
    const int nN4 = NN_NODES * CN / 4;

    const int SME = 2 * (256 + 64) * 20 * 4;     // 51200
    const int SMN = 2 * (128 + 128) * 20 * 4;    // 40960
    cudaFuncSetAttribute(hmma_gemm<2, 1>, cudaFuncAttributeMaxDynamicSharedMemorySize, SME);
    cudaFuncSetAttribute(hmma_gemm<2, 2>, cudaFuncAttributeMaxDynamicSharedMemorySize, SMN);

    static cudaStream_t s2 = make_stream();
    static cudaEvent_t evW   = make_event();
    static cudaEvent_t evQN1 = make_event();
    static cudaEvent_t evBr1 = make_event();
    static cudaEvent_t evEf2 = make_event();

    // ===== main: CSR + weights + constants + brf convert =====
    csr_build<MPG, MPG * 4><<<BGR, 256>>>(srcE, dstE, offE, adjE);
    csr_build<NPG, EPG><<<BGR, 256>>>(srcN, dstN, offN, adjN);
    wsplit_all<<<(W_TOT + 255) / 256, 256>>>(WqE1, WkE1, WvE1, WqE2, WkE2, WvE2,
                                             We1, We2, Wq1, Wk1, Wv1, Wq2, Wk2, Wv2, whi);
    onehot_fill4<<<(BGR * NPG * (CE / 4)) / 256, 256>>>((float4*)ei2_buf);
    cvt_f16<<<(nE2 + 255) / 256, 256>>>((const float2*)brf, ahiE, nE2);
    cudaEventRecord(evW, 0);
    cudaStreamWaitEvent(s2, evW, 0);

    // ===== stream2: N1 prep =====
    cvt_f16<<<(nN2 + 255) / 256, 256, 0, s2>>>((const float2*)x, ahiN, nN2);
    hmma_gemm<2, 2><<<dim3(6, NN_NODES / 128), 256, SMN, s2>>>(
        ahiN, whi + W_N1, qN, kN, vN, NN_NODES, CN, 256, 2);
    cudaEventRecord(evQN1, s2);

    // ===== main: E1 chain =====
    hmma_gemm<2, 1><<<dim3(3, NE_NODES / 256), 256, SME>>>(
        ahiE, whi + W_E1, qE, kE, vE, NE_NODES, CE, 64, 1);
    attn_conv<CE, 4, MPG, MPG * 4, false><<<BGR, 256>>>(
        qE, kE, vE, nullptr, nullptr, offE, adjE, accE, bnpartE, scaleE);
    bn_final3<CE><<<CE, 256>>>(bnpartE, muE, rstdE, BGR, NE_NODES);
    bn_apply4s<CE, false><<<nE4 / 256, 256>>>(
        (const float4*)accE, (const float4*)brf, muE, rstdE, gE1, bE1,
        (float4*)br1, (uint2*)ahiE, nE4);
    cudaEventRecord(evBr1, 0);
    cudaStreamWaitEvent(s2, evBr1, 0);

    // ===== main: ef1 + N1 attn chain =====
    hmma_gemm<2, 2><<<dim3(2, NE_NODES / 128), 256, SMN>>>(
        ahiE, whi + W_WE1, efbr, efbr, efbr, NE_NODES, CE, 256, 2);
    cudaStreamWaitEvent(0, evQN1, 0);
    attn_conv<CN, 4, NPG, EPG, true><<<BGR, 256>>>(
        qN, kN, vN, efbr, We1, offN, adjN, accN, bnpartN, scaleN);
    bn_final3<CN><<<CN, 256>>>(bnpartN, muN, rstdN, BGR, NN_NODES);
    bn_apply4s<CN, false><<<nN4 / 256, 256>>>(
        (const float4*)accN, (const float4*)x, muN, rstdN, gN1, bN1,
        (float4*)out1, (uint2*)ahiN, nN4);

    // ===== stream2: E2 chain =====
    hmma_gemm<2, 1><<<dim3(3, NE_NODES / 256), 256, SME, s2>>>(
        ahiE, whi + W_E2, qE, kE, vE, NE_NODES, CE, 64, 1);
    attn_conv<CE, 4, MPG, MPG * 4, false><<<BGR, 256, 0, s2>>>(
        qE, kE, vE, nullptr, nullptr, offE, adjE, accE, bnpartE, scaleE);
    bn_final3<CE><<<CE, 256, 0, s2>>>(bnpartE, muE, rstdE, BGR, NE_NODES);
    bn_apply_toedge4<<<nE4 / 256, 256, 0, s2>>>(
        (const float4*)accE, (const float4*)br1, muE, rstdE, gE2, bE2,
        (float4*)br2_buf, (float4*)ei2_buf, (uint2*)ahiE2);
    hmma_gemm<2, 2><<<dim3(2, NE_NODES / 128), 256, SMN, s2>>>(
        ahiE2, whi + W_WE2, efbr2, efbr2, efbr2, NE_NODES, CE, 256, 2);
    cudaEventRecord(evEf2, s2);

    // ===== main: N2 chain =====
    hmma_gemm<2, 2><<<dim3(6, NN_NODES / 128), 256, SMN>>>(
        ahiN, whi + W_N2, qN, kN, vN, NN_NODES, CN, 256, 2);
    cudaStreamWaitEvent(0, evEf2, 0);
    attn_conv<CN, 4, NPG, EPG, true><<<BGR, 256>>>(
        qN, kN, vN, efbr2, We2, offN, adjN, accN, bnpartN, scaleN);
    bn_final3<CN><<<CN, 256>>>(bnpartN, muN, rstdN, BGR, NN_NODES);
    bn_apply_sn4<<<nN4 / 256, 256>>>(
        (const float4*)accN, (const float4*)out1, muN, rstdN, gN2, bN2,
        (float4*)out2_buf, (float4*)sn_buf);
}